// round 2
// baseline (speedup 1.0000x reference)
#include <cuda_runtime.h>
#include <cuda_bf16.h>
#include <stdint.h>
#include <math.h>

#define BB 4096
#define FF 256
#define HH 256
#define MM 3
#define TT 30
#define G3 768
#define IN0 258
#define KP 72

typedef __nv_bfloat16 bf16;

// ---------- device scratch (no allocation allowed) ----------
__device__ bf16 g_ctx_hi[BB*FF], g_ctx_lo[BB*FF];
__device__ bf16 g_h0_hi[2][MM*BB*HH], g_h0_lo[2][MM*BB*HH];
__device__ bf16 g_h1_hi[2][MM*BB*HH], g_h1_lo[2][MM*BB*HH];
__device__ bf16 g_whh0_hi[MM*G3*HH], g_whh0_lo[MM*G3*HH];
__device__ bf16 g_wih1_hi[MM*G3*HH], g_wih1_lo[MM*G3*HH];
__device__ bf16 g_whh1_hi[MM*G3*HH], g_whh1_lo[MM*G3*HH];
__device__ bf16 g_wc_hi[MM*G3*HH],   g_wc_lo[MM*G3*HH];   // w_ih0[:, :, 2:]
__device__ float g_gx0[(size_t)MM*BB*G3];
__device__ float g_s0[(size_t)MM*BB*G3];
__device__ float g_s1[(size_t)MM*BB*G3];
__device__ float g_s2[(size_t)MM*BB*G3];
__device__ float g_h1f[MM*BB*HH];
__device__ float g_delta[MM*BB*2], g_cum[MM*BB*2];

__device__ __forceinline__ void mma16816(float* d, const uint32_t* a, const uint32_t* b) {
    asm volatile(
        "mma.sync.aligned.m16n8k16.row.col.f32.bf16.bf16.f32 "
        "{%0,%1,%2,%3}, {%4,%5,%6,%7}, {%8,%9}, {%0,%1,%2,%3};\n"
        : "+f"(d[0]), "+f"(d[1]), "+f"(d[2]), "+f"(d[3])
        : "r"(a[0]), "r"(a[1]), "r"(a[2]), "r"(a[3]), "r"(b[0]), "r"(b[1]));
}
__device__ __forceinline__ void splitb(float v, bf16& hi, bf16& lo) {
    hi = __float2bfloat16(v);
    lo = __float2bfloat16(v - __bfloat162float(hi));
}

// ---------- prep ----------
__global__ void k_prep_ctx(const float* __restrict__ ctx) {
    int i = blockIdx.x * blockDim.x + threadIdx.x;
    if (i >= BB * FF) return;
    bf16 hi, lo; splitb(ctx[i], hi, lo);
    g_ctx_hi[i] = hi; g_ctx_lo[i] = lo;
#pragma unroll
    for (int m = 0; m < MM; m++) {
        int o = m * BB * HH + i;
        g_h0_hi[0][o] = hi; g_h0_lo[0][o] = lo;
        g_h1_hi[0][o] = hi; g_h1_lo[0][o] = lo;
    }
}

__global__ void k_prep_w(const float* __restrict__ whh0, const float* __restrict__ wih1,
                         const float* __restrict__ whh1, const float* __restrict__ wih0) {
    const int n1 = MM * G3 * HH;
    int i = blockIdx.x * blockDim.x + threadIdx.x;
    if (i >= 4 * n1) return;
    int a = i / n1, e = i - a * n1;
    float v;
    if (a == 3) {
        int m = e / (G3 * HH), r = (e - m * G3 * HH) / HH, c = e % HH;
        v = wih0[((size_t)m * G3 + r) * IN0 + 2 + c];
    } else v = (a == 0 ? whh0 : (a == 1 ? wih1 : whh1))[e];
    bf16 hi, lo; splitb(v, hi, lo);
    if      (a == 0) { g_whh0_hi[e] = hi; g_whh0_lo[e] = lo; }
    else if (a == 1) { g_wih1_hi[e] = hi; g_wih1_lo[e] = lo; }
    else if (a == 2) { g_whh1_hi[e] = hi; g_whh1_lo[e] = lo; }
    else             { g_wc_hi[e]   = hi; g_wc_lo[e]   = lo; }
}

__global__ void k_prep_zero() {
    int i = blockIdx.x * blockDim.x + threadIdx.x;
    if (i < MM * BB * 2) { g_delta[i] = 0.f; g_cum[i] = 0.f; }
}

// ---------- mode probs ----------
__global__ void k_modeprobs(const float* __restrict__ ctx,
                            const float* __restrict__ w1, const float* __restrict__ b1,
                            const float* __restrict__ w2, const float* __restrict__ b2,
                            float* __restrict__ probs) {
    int gw = (blockIdx.x * blockDim.x + threadIdx.x) >> 5;
    int lane = threadIdx.x & 31;
    int b0 = gw * 4;
    if (b0 >= BB) return;
    int u0 = lane * 2, u1 = u0 + 1;
    float acc[4][2];
#pragma unroll
    for (int r = 0; r < 4; r++) { acc[r][0] = 0.f; acc[r][1] = 0.f; }
    for (int k = 0; k < FF; k++) {
        float wa = __ldg(&w1[u0 * FF + k]), wb = __ldg(&w1[u1 * FF + k]);
#pragma unroll
        for (int r = 0; r < 4; r++) {
            float c = __ldg(&ctx[(size_t)(b0 + r) * FF + k]);
            acc[r][0] += c * wa; acc[r][1] += c * wb;
        }
    }
#pragma unroll
    for (int r = 0; r < 4; r++) {
        float h0v = fmaxf(acc[r][0] + b1[u0], 0.f);
        float h1v = fmaxf(acc[r][1] + b1[u1], 0.f);
        float lg[3];
#pragma unroll
        for (int m = 0; m < 3; m++) {
            float p = h0v * w2[m * 64 + u0] + h1v * w2[m * 64 + u1];
#pragma unroll
            for (int o = 16; o; o >>= 1) p += __shfl_xor_sync(0xffffffffu, p, o);
            lg[m] = p + b2[m];
        }
        if (lane == 0) {
            float mx = fmaxf(lg[0], fmaxf(lg[1], lg[2]));
            float e0 = expf(lg[0]-mx), e1 = expf(lg[1]-mx), e2 = expf(lg[2]-mx);
            float s = e0 + e1 + e2;
            probs[(size_t)(b0+r)*MM+0] = e0/s;
            probs[(size_t)(b0+r)*MM+1] = e1/s;
            probs[(size_t)(b0+r)*MM+2] = e2/s;
        }
    }
}

// ---------- generic bf16x3 GEMM: C[m] = A[m] @ W[m]^T, fp32 accum ----------
// sel: 0=gx0(ctx@wc), 1=gh0(h0[p]@whh0), 2=gx1(h0[p^1]@wih1), 3=gh1(h1[p]@whh1)
__global__ void __launch_bounds__(128) k_gemm(int sel, int p) {
    const int m = blockIdx.z, rb = blockIdx.x, ub = blockIdx.y;
    __shared__ __align__(16) bf16 sm[(2*64 + 2*32) * KP];
    bf16* As = sm;
    bf16* Ws = sm + 2*64*KP;

    const bf16 *Ahi, *Alo, *Whi, *Wlo; float* C;
    if (sel == 0)      { Ahi = g_ctx_hi;        Alo = g_ctx_lo;
                         Whi = g_wc_hi;         Wlo = g_wc_lo;   C = g_gx0; }
    else if (sel == 1) { Ahi = g_h0_hi[p]   + m*BB*HH; Alo = g_h0_lo[p]   + m*BB*HH;
                         Whi = g_whh0_hi;       Wlo = g_whh0_lo; C = g_s0; }
    else if (sel == 2) { Ahi = g_h0_hi[p^1] + m*BB*HH; Alo = g_h0_lo[p^1] + m*BB*HH;
                         Whi = g_wih1_hi;       Wlo = g_wih1_lo; C = g_s1; }
    else               { Ahi = g_h1_hi[p]   + m*BB*HH; Alo = g_h1_lo[p]   + m*BB*HH;
                         Whi = g_whh1_hi;       Wlo = g_whh1_lo; C = g_s2; }
    Whi += m * G3 * HH; Wlo += m * G3 * HH;

    const int tid = threadIdx.x, lane = tid & 31, wid = tid >> 5;
    const int wm = wid & 1, wn = wid >> 1, gq = lane >> 2, tg = lane & 3;
    const bf16* Ap[2] = { Ahi, Alo };
    const bf16* Wp[2] = { Whi, Wlo };

    float acc[2][2][4];
#pragma unroll
    for (int a = 0; a < 2; a++)
#pragma unroll
        for (int b = 0; b < 2; b++)
#pragma unroll
            for (int e = 0; e < 4; e++) acc[a][b][e] = 0.f;

    for (int kc = 0; kc < 4; kc++) {
        const int k0 = kc * 64;
        for (int idx = tid; idx < 1024; idx += 128) {        // A: 2 x 64row x 8 uint4
            int t = idx >> 9, rem = idx & 511, r = rem >> 3, c = rem & 7;
            ((uint4*)As)[t*64*9 + r*9 + c] =
                ((const uint4*)(Ap[t] + (size_t)(rb*64 + r)*HH + k0))[c];
        }
        for (int idx = tid; idx < 512; idx += 128) {         // W: 2 x 32row x 8 uint4
            int t = idx >> 8, rem = idx & 255, r = rem >> 3, c = rem & 7;
            ((uint4*)Ws)[t*32*9 + r*9 + c] =
                ((const uint4*)(Wp[t] + (size_t)(ub*32 + r)*HH + k0))[c];
        }
        __syncthreads();
#pragma unroll
        for (int ks = 0; ks < 4; ks++) {
            const int kk = ks * 16;
            uint32_t afr[2][2][4];
#pragma unroll
            for (int hl = 0; hl < 2; hl++)
#pragma unroll
                for (int mf = 0; mf < 2; mf++) {
                    const bf16* at = As + hl*64*KP + (wm*32 + mf*16 + gq)*KP + kk + tg*2;
                    afr[hl][mf][0] = *(const uint32_t*)at;
                    afr[hl][mf][1] = *(const uint32_t*)(at + 8*KP);
                    afr[hl][mf][2] = *(const uint32_t*)(at + 8);
                    afr[hl][mf][3] = *(const uint32_t*)(at + 8*KP + 8);
                }
            uint32_t bfr[2][2][2];
#pragma unroll
            for (int hl = 0; hl < 2; hl++)
#pragma unroll
                for (int nf = 0; nf < 2; nf++) {
                    const bf16* wt = Ws + hl*32*KP + (wn*16 + nf*8 + gq)*KP + kk + tg*2;
                    bfr[hl][nf][0] = *(const uint32_t*)wt;
                    bfr[hl][nf][1] = *(const uint32_t*)(wt + 8);
                }
#pragma unroll
            for (int mf = 0; mf < 2; mf++)
#pragma unroll
                for (int nf = 0; nf < 2; nf++) {
                    mma16816(acc[mf][nf], afr[0][mf], bfr[0][nf]);   // hi*hi
                    mma16816(acc[mf][nf], afr[0][mf], bfr[1][nf]);   // hi*lo
                    mma16816(acc[mf][nf], afr[1][mf], bfr[0][nf]);   // lo*hi
                }
        }
        __syncthreads();
    }
#pragma unroll
    for (int mf = 0; mf < 2; mf++)
#pragma unroll
        for (int e = 0; e < 2; e++) {
            int row = rb*64 + wm*32 + mf*16 + gq + e*8;
#pragma unroll
            for (int nf = 0; nf < 2; nf++)
#pragma unroll
                for (int cc = 0; cc < 2; cc++) {
                    int col = ub*32 + wn*16 + nf*8 + tg*2 + cc;
                    C[((size_t)m*BB + row)*G3 + col] = acc[mf][nf][e*2 + cc];
                }
        }
}

// ---------- gates ----------
__global__ void k_gates0(const float* __restrict__ wih0, const float* __restrict__ bih0,
                         const float* __restrict__ bhh0, int p) {
    int i = blockIdx.x * blockDim.x + threadIdx.x;
    if (i >= MM*BB*HH) return;
    int m = i / (BB*HH), rem = i - m*BB*HH;
    int b = rem / HH, u = rem - b*HH;
    size_t base = (size_t)(m*BB + b) * G3;
    float px = g_delta[(m*BB+b)*2+0], py = g_delta[(m*BB+b)*2+1];
    const float* wr = wih0 + (size_t)(m*G3 + u)*IN0;
    const float* wz = wih0 + (size_t)(m*G3 + HH + u)*IN0;
    const float* wn = wih0 + (size_t)(m*G3 + 2*HH + u)*IN0;
    float xr = g_gx0[base+u]      + px*wr[0] + py*wr[1] + bih0[m*G3+u];
    float xz = g_gx0[base+HH+u]   + px*wz[0] + py*wz[1] + bih0[m*G3+HH+u];
    float xn = g_gx0[base+2*HH+u] + px*wn[0] + py*wn[1] + bih0[m*G3+2*HH+u];
    float hr = g_s0[base+u]       + bhh0[m*G3+u];
    float hz = g_s0[base+HH+u]    + bhh0[m*G3+HH+u];
    float hn = g_s0[base+2*HH+u]  + bhh0[m*G3+2*HH+u];
    float r = 1.f/(1.f+expf(-(xr+hr)));
    float z = 1.f/(1.f+expf(-(xz+hz)));
    float n = tanhf(xn + r*hn);
    float hp = __bfloat162float(g_h0_hi[p][i]) + __bfloat162float(g_h0_lo[p][i]);
    float h = (1.f-z)*n + z*hp;
    bf16 hi; bf16 lo; splitb(h, hi, lo);
    g_h0_hi[p^1][i] = hi; g_h0_lo[p^1][i] = lo;
}

__global__ void k_gates1(const float* __restrict__ bih1, const float* __restrict__ bhh1, int p) {
    int i = blockIdx.x * blockDim.x + threadIdx.x;
    if (i >= MM*BB*HH) return;
    int m = i / (BB*HH), rem = i - m*BB*HH;
    int b = rem / HH, u = rem - b*HH;
    size_t base = (size_t)(m*BB + b) * G3;
    float xr = g_s1[base+u]      + bih1[m*G3+u];
    float xz = g_s1[base+HH+u]   + bih1[m*G3+HH+u];
    float xn = g_s1[base+2*HH+u] + bih1[m*G3+2*HH+u];
    float hr = g_s2[base+u]      + bhh1[m*G3+u];
    float hz = g_s2[base+HH+u]   + bhh1[m*G3+HH+u];
    float hn = g_s2[base+2*HH+u] + bhh1[m*G3+2*HH+u];
    float r = 1.f/(1.f+expf(-(xr+hr)));
    float z = 1.f/(1.f+expf(-(xz+hz)));
    float n = tanhf(xn + r*hn);
    float hp = __bfloat162float(g_h1_hi[p][i]) + __bfloat162float(g_h1_lo[p][i]);
    float h = (1.f-z)*n + z*hp;
    bf16 hi; bf16 lo; splitb(h, hi, lo);
    g_h1_hi[p^1][i] = hi; g_h1_lo[p^1][i] = lo;
    g_h1f[i] = h;
}

// ---------- delta + cumsum + output ----------
__global__ void k_delta(const float* __restrict__ ow, const float* __restrict__ ob,
                        float* __restrict__ out, int t) {
    int warp = (blockIdx.x * blockDim.x + threadIdx.x) >> 5;
    int lane = threadIdx.x & 31;
    if (warp >= MM*BB) return;
    int m = warp / BB, b = warp - m*BB;
    const float* h = g_h1f + (size_t)warp * HH;
    float a0 = 0.f, a1 = 0.f;
    for (int k = lane; k < HH; k += 32) {
        float hv = h[k];
        a0 += hv * __ldg(&ow[(m*2+0)*HH + k]);
        a1 += hv * __ldg(&ow[(m*2+1)*HH + k]);
    }
#pragma unroll
    for (int o = 16; o; o >>= 1) {
        a0 += __shfl_xor_sync(0xffffffffu, a0, o);
        a1 += __shfl_xor_sync(0xffffffffu, a1, o);
    }
    if (lane == 0) {
        a0 += ob[m*2+0]; a1 += ob[m*2+1];
        g_delta[warp*2+0] = a0; g_delta[warp*2+1] = a1;
        float c0 = g_cum[warp*2+0] + a0, c1 = g_cum[warp*2+1] + a1;
        g_cum[warp*2+0] = c0; g_cum[warp*2+1] = c1;
        size_t oo = (((size_t)b*MM + m)*TT + t)*2;
        out[oo] = c0; out[oo+1] = c1;
    }
}

// ---------- launch ----------
extern "C" void kernel_launch(void* const* d_in, const int* in_sizes, int n_in,
                              void* d_out, int out_size) {
    const float* ctx  = (const float*)d_in[0];
    const float* w1   = (const float*)d_in[1];
    const float* b1   = (const float*)d_in[2];
    const float* w2   = (const float*)d_in[3];
    const float* b2   = (const float*)d_in[4];
    const float* wih0 = (const float*)d_in[5];
    const float* whh0 = (const float*)d_in[6];
    const float* bih0 = (const float*)d_in[7];
    const float* bhh0 = (const float*)d_in[8];
    const float* wih1 = (const float*)d_in[9];
    const float* whh1 = (const float*)d_in[10];
    const float* bih1 = (const float*)d_in[11];
    const float* bhh1 = (const float*)d_in[12];
    const float* ow   = (const float*)d_in[13];
    const float* ob   = (const float*)d_in[14];
    float* out = (float*)d_out;
    float* probs = out + (size_t)BB*MM*TT*2;

    k_prep_ctx<<<(BB*FF)/256, 256>>>(ctx);
    k_prep_w<<<(4*MM*G3*HH)/256, 256>>>(whh0, wih1, whh1, wih0);
    k_prep_zero<<<96, 256>>>();
    k_modeprobs<<<256, 128>>>(ctx, w1, b1, w2, b2, probs);

    dim3 gg(BB/64, G3/32, MM);
    k_gemm<<<gg, 128>>>(0, 0);   // gx0 context part (once)

    const int NE = MM*BB*HH;
    for (int t = 0; t < TT; t++) {
        int p = t & 1;
        k_gemm<<<gg, 128>>>(1, p);                       // gh0 = h0[p] @ whh0^T
        k_gates0<<<(NE+255)/256, 256>>>(wih0, bih0, bhh0, p);
        k_gemm<<<gg, 128>>>(2, p);                       // gx1 = h0[p^1] @ wih1^T
        k_gemm<<<gg, 128>>>(3, p);                       // gh1 = h1[p] @ whh1^T
        k_gates1<<<(NE+255)/256, 256>>>(bih1, bhh1, p);
        k_delta<<<(MM*BB*32+127)/128, 128>>>(ow, ob, out, t);
    }
}

// round 3
// speedup vs baseline: 1.1601x; 1.1601x over previous
#include <cuda_runtime.h>
#include <cuda_bf16.h>
#include <stdint.h>
#include <math.h>

#define BB 4096
#define FF 256
#define HH 256
#define MM 3
#define TT 30
#define G3 768
#define IN0 258
#define KP 72

typedef __nv_bfloat16 bf16;

__device__ bf16 g_ctx_hi[BB*FF], g_ctx_lo[BB*FF];
__device__ bf16 g_h0_hi[2][MM*BB*HH], g_h0_lo[2][MM*BB*HH];
__device__ bf16 g_h1_hi[2][MM*BB*HH], g_h1_lo[2][MM*BB*HH];
__device__ bf16 g_whh0_hi[MM*G3*HH], g_whh0_lo[MM*G3*HH];
__device__ bf16 g_wih1_hi[MM*G3*HH], g_wih1_lo[MM*G3*HH];
__device__ bf16 g_whh1_hi[MM*G3*HH], g_whh1_lo[MM*G3*HH];
__device__ bf16 g_wc_hi[MM*G3*HH],   g_wc_lo[MM*G3*HH];
__device__ float g_gx0[(size_t)MM*BB*G3];
__device__ float g_h1f[MM*BB*HH];
__device__ float g_delta[MM*BB*2], g_cum[MM*BB*2];

__device__ __forceinline__ void mma16816(float* d, const uint32_t* a, const uint32_t* b) {
    asm volatile(
        "mma.sync.aligned.m16n8k16.row.col.f32.bf16.bf16.f32 "
        "{%0,%1,%2,%3}, {%4,%5,%6,%7}, {%8,%9}, {%0,%1,%2,%3};\n"
        : "+f"(d[0]), "+f"(d[1]), "+f"(d[2]), "+f"(d[3])
        : "r"(a[0]), "r"(a[1]), "r"(a[2]), "r"(a[3]), "r"(b[0]), "r"(b[1]));
}
__device__ __forceinline__ void splitb(float v, bf16& hi, bf16& lo) {
    hi = __float2bfloat16(v);
    lo = __float2bfloat16(v - __bfloat162float(hi));
}
__device__ __forceinline__ float sigf(float x) { return 1.f/(1.f+expf(-x)); }

// ---------- prep ----------
__global__ void k_prep_ctx(const float* __restrict__ ctx) {
    int i = blockIdx.x * blockDim.x + threadIdx.x;
    if (i >= BB * FF) return;
    bf16 hi, lo; splitb(ctx[i], hi, lo);
    g_ctx_hi[i] = hi; g_ctx_lo[i] = lo;
#pragma unroll
    for (int m = 0; m < MM; m++) {
        int o = m * BB * HH + i;
        g_h0_hi[0][o] = hi; g_h0_lo[0][o] = lo;
        g_h1_hi[0][o] = hi; g_h1_lo[0][o] = lo;
    }
}
__global__ void k_prep_w(const float* __restrict__ whh0, const float* __restrict__ wih1,
                         const float* __restrict__ whh1, const float* __restrict__ wih0) {
    const int n1 = MM * G3 * HH;
    int i = blockIdx.x * blockDim.x + threadIdx.x;
    if (i >= 4 * n1) return;
    int a = i / n1, e = i - a * n1;
    float v;
    if (a == 3) {
        int m = e / (G3 * HH), r = (e - m * G3 * HH) / HH, c = e % HH;
        v = wih0[((size_t)m * G3 + r) * IN0 + 2 + c];
    } else v = (a == 0 ? whh0 : (a == 1 ? wih1 : whh1))[e];
    bf16 hi, lo; splitb(v, hi, lo);
    if      (a == 0) { g_whh0_hi[e] = hi; g_whh0_lo[e] = lo; }
    else if (a == 1) { g_wih1_hi[e] = hi; g_wih1_lo[e] = lo; }
    else if (a == 2) { g_whh1_hi[e] = hi; g_whh1_lo[e] = lo; }
    else             { g_wc_hi[e]   = hi; g_wc_lo[e]   = lo; }
}
__global__ void k_prep_zero() {
    int i = blockIdx.x * blockDim.x + threadIdx.x;
    if (i < MM * BB * 2) { g_delta[i] = 0.f; g_cum[i] = 0.f; }
}

// ---------- mode probs ----------
__global__ void k_modeprobs(const float* __restrict__ ctx,
                            const float* __restrict__ w1, const float* __restrict__ b1,
                            const float* __restrict__ w2, const float* __restrict__ b2,
                            float* __restrict__ probs) {
    int gw = (blockIdx.x * blockDim.x + threadIdx.x) >> 5;
    int lane = threadIdx.x & 31;
    int b0 = gw * 4;
    if (b0 >= BB) return;
    int u0 = lane * 2, u1 = u0 + 1;
    float acc[4][2];
#pragma unroll
    for (int r = 0; r < 4; r++) { acc[r][0] = 0.f; acc[r][1] = 0.f; }
    for (int k = 0; k < FF; k++) {
        float wa = __ldg(&w1[u0*FF+k]), wb = __ldg(&w1[u1*FF+k]);
#pragma unroll
        for (int r = 0; r < 4; r++) {
            float c = __ldg(&ctx[(size_t)(b0+r)*FF+k]);
            acc[r][0] += c*wa; acc[r][1] += c*wb;
        }
    }
#pragma unroll
    for (int r = 0; r < 4; r++) {
        float h0v = fmaxf(acc[r][0] + b1[u0], 0.f);
        float h1v = fmaxf(acc[r][1] + b1[u1], 0.f);
        float lg[3];
#pragma unroll
        for (int m = 0; m < 3; m++) {
            float p = h0v*w2[m*64+u0] + h1v*w2[m*64+u1];
#pragma unroll
            for (int o = 16; o; o >>= 1) p += __shfl_xor_sync(0xffffffffu, p, o);
            lg[m] = p + b2[m];
        }
        if (lane == 0) {
            float mx = fmaxf(lg[0], fmaxf(lg[1], lg[2]));
            float e0 = expf(lg[0]-mx), e1 = expf(lg[1]-mx), e2 = expf(lg[2]-mx);
            float s = e0+e1+e2;
            probs[(size_t)(b0+r)*MM+0] = e0/s;
            probs[(size_t)(b0+r)*MM+1] = e1/s;
            probs[(size_t)(b0+r)*MM+2] = e2/s;
        }
    }
}

// ---------- gx0 = ctx @ wc^T (once), 128 thr, Mtile 64, Ntile 32 ----------
__global__ void __launch_bounds__(128) k_gx0() {
    const int m = blockIdx.z, rb = blockIdx.x, ub = blockIdx.y;
    __shared__ __align__(16) bf16 sm[(2*64 + 2*32) * KP];
    bf16* As = sm; bf16* Ws = sm + 2*64*KP;
    const bf16* Ap[2] = { g_ctx_hi, g_ctx_lo };
    const bf16* Wp[2] = { g_wc_hi + m*G3*HH, g_wc_lo + m*G3*HH };
    const int tid = threadIdx.x, lane = tid & 31, wid = tid >> 5;
    const int wm = wid & 1, wn = wid >> 1, gq = lane >> 2, tg = lane & 3;
    float acc[2][2][4];
#pragma unroll
    for (int a = 0; a < 2; a++)
#pragma unroll
    for (int b = 0; b < 2; b++)
#pragma unroll
    for (int e = 0; e < 4; e++) acc[a][b][e] = 0.f;

    for (int kc = 0; kc < 4; kc++) {
        const int k0 = kc * 64;
        for (int idx = tid; idx < 1024; idx += 128) {
            int t = idx >> 9, rem = idx & 511, r = rem >> 3, c = rem & 7;
            ((uint4*)As)[t*64*9 + r*9 + c] = ((const uint4*)(Ap[t] + (size_t)(rb*64+r)*HH + k0))[c];
        }
        for (int idx = tid; idx < 512; idx += 128) {
            int t = idx >> 8, rem = idx & 255, r = rem >> 3, c = rem & 7;
            ((uint4*)Ws)[t*32*9 + r*9 + c] = ((const uint4*)(Wp[t] + (size_t)(ub*32+r)*HH + k0))[c];
        }
        __syncthreads();
#pragma unroll
        for (int ks = 0; ks < 4; ks++) {
            const int kk = ks * 16;
            uint32_t afr[2][2][4];
#pragma unroll
            for (int hl = 0; hl < 2; hl++)
#pragma unroll
                for (int mf = 0; mf < 2; mf++) {
                    const bf16* at = As + hl*64*KP + (wm*32+mf*16+gq)*KP + kk + tg*2;
                    afr[hl][mf][0] = *(const uint32_t*)at;
                    afr[hl][mf][1] = *(const uint32_t*)(at + 8*KP);
                    afr[hl][mf][2] = *(const uint32_t*)(at + 8);
                    afr[hl][mf][3] = *(const uint32_t*)(at + 8*KP + 8);
                }
            uint32_t bfr[2][2][2];
#pragma unroll
            for (int hl = 0; hl < 2; hl++)
#pragma unroll
                for (int nf = 0; nf < 2; nf++) {
                    const bf16* wt = Ws + hl*32*KP + (wn*16+nf*8+gq)*KP + kk + tg*2;
                    bfr[hl][nf][0] = *(const uint32_t*)wt;
                    bfr[hl][nf][1] = *(const uint32_t*)(wt + 8);
                }
#pragma unroll
            for (int mf = 0; mf < 2; mf++)
#pragma unroll
                for (int nf = 0; nf < 2; nf++) {
                    mma16816(acc[mf][nf], afr[0][mf], bfr[0][nf]);
                    mma16816(acc[mf][nf], afr[0][mf], bfr[1][nf]);
                    mma16816(acc[mf][nf], afr[1][mf], bfr[0][nf]);
                }
        }
        __syncthreads();
    }
#pragma unroll
    for (int mf = 0; mf < 2; mf++)
#pragma unroll
    for (int e = 0; e < 2; e++) {
        int row = rb*64 + wm*32 + mf*16 + gq + e*8;
#pragma unroll
        for (int nf = 0; nf < 2; nf++)
#pragma unroll
        for (int cc = 0; cc < 2; cc++) {
            int col = ub*32 + wn*16 + nf*8 + tg*2 + cc;
            g_gx0[((size_t)m*BB+row)*G3 + col] = acc[mf][nf][e*2+cc];
        }
    }
}

// ---------- layer0 fused: gh0 + gates, Mtile 64, Utile 32, 256 thr ----------
__global__ void __launch_bounds__(256) k_l0(const float* __restrict__ wih0,
                                            const float* __restrict__ bih0,
                                            const float* __restrict__ bhh0, int p) {
    const int m = blockIdx.z, rb = blockIdx.x, ub = blockIdx.y, q = p^1;
    __shared__ __align__(16) bf16 sm[(2*64 + 6*32) * KP];
    bf16* As = sm; bf16* Ws = sm + 2*64*KP;
    const bf16* Ap[2] = { g_h0_hi[p] + m*BB*HH, g_h0_lo[p] + m*BB*HH };
    const bf16* Wp[2] = { g_whh0_hi + m*G3*HH, g_whh0_lo + m*G3*HH };
    const int tid = threadIdx.x, lane = tid & 31, wid = tid >> 5;
    const int wm = wid >> 1, wn = wid & 1, gq = lane >> 2, tg = lane & 3;
    float acc[3][2][4];
#pragma unroll
    for (int g = 0; g < 3; g++)
#pragma unroll
    for (int b = 0; b < 2; b++)
#pragma unroll
    for (int e = 0; e < 4; e++) acc[g][b][e] = 0.f;

    for (int kc = 0; kc < 4; kc++) {
        const int k0 = kc * 64;
        for (int idx = tid; idx < 1024; idx += 256) {
            int t = idx >> 9, rem = idx & 511, r = rem >> 3, c = rem & 7;
            ((uint4*)As)[t*64*9 + r*9 + c] = ((const uint4*)(Ap[t] + (size_t)(rb*64+r)*HH + k0))[c];
        }
        for (int idx = tid; idx < 1536; idx += 256) {   // 6 tiles (hl*3+g) x 32 x 8
            int t = idx >> 8, rem = idx & 255, r = rem >> 3, c = rem & 7;
            int hl = t / 3, g = t % 3;
            ((uint4*)Ws)[t*32*9 + r*9 + c] =
                ((const uint4*)(Wp[hl] + (size_t)(g*HH + ub*32 + r)*HH + k0))[c];
        }
        __syncthreads();
#pragma unroll
        for (int ks = 0; ks < 4; ks++) {
            const int kk = ks * 16;
            uint32_t afr[2][4];
#pragma unroll
            for (int hl = 0; hl < 2; hl++) {
                const bf16* at = As + (hl*64 + wm*16 + gq)*KP + kk + tg*2;
                afr[hl][0] = *(const uint32_t*)at;
                afr[hl][1] = *(const uint32_t*)(at + 8*KP);
                afr[hl][2] = *(const uint32_t*)(at + 8);
                afr[hl][3] = *(const uint32_t*)(at + 8*KP + 8);
            }
#pragma unroll
            for (int g = 0; g < 3; g++) {
                uint32_t bfr[2][2][2];
#pragma unroll
                for (int hl = 0; hl < 2; hl++)
#pragma unroll
                    for (int nf = 0; nf < 2; nf++) {
                        const bf16* wt = Ws + ((hl*3+g)*32 + wn*16+nf*8+gq)*KP + kk + tg*2;
                        bfr[hl][nf][0] = *(const uint32_t*)wt;
                        bfr[hl][nf][1] = *(const uint32_t*)(wt + 8);
                    }
#pragma unroll
                for (int nf = 0; nf < 2; nf++) {
                    mma16816(acc[g][nf], afr[0], bfr[0][nf]);
                    mma16816(acc[g][nf], afr[0], bfr[1][nf]);
                    mma16816(acc[g][nf], afr[1], bfr[0][nf]);
                }
            }
        }
        __syncthreads();
    }
    const float* bi = bih0 + m*G3; const float* bh = bhh0 + m*G3;
#pragma unroll
    for (int e = 0; e < 2; e++) {
        int row = rb*64 + wm*16 + gq + e*8;
        float px = g_delta[(m*BB+row)*2+0], py = g_delta[(m*BB+row)*2+1];
        size_t gxb = (size_t)(m*BB+row)*G3;
#pragma unroll
        for (int nf = 0; nf < 2; nf++)
#pragma unroll
        for (int cc = 0; cc < 2; cc++) {
            int u = ub*32 + wn*16 + nf*8 + tg*2 + cc;
            const float* wr = wih0 + (size_t)(m*G3+u)*IN0;
            const float* wz = wih0 + (size_t)(m*G3+HH+u)*IN0;
            const float* wn2 = wih0 + (size_t)(m*G3+2*HH+u)*IN0;
            float xr = g_gx0[gxb+u]      + px*wr[0]  + py*wr[1]  + bi[u];
            float xz = g_gx0[gxb+HH+u]   + px*wz[0]  + py*wz[1]  + bi[HH+u];
            float xn = g_gx0[gxb+2*HH+u] + px*wn2[0] + py*wn2[1] + bi[2*HH+u];
            float r = sigf(xr + acc[0][nf][e*2+cc] + bh[u]);
            float z = sigf(xz + acc[1][nf][e*2+cc] + bh[HH+u]);
            float n = tanhf(xn + r*(acc[2][nf][e*2+cc] + bh[2*HH+u]));
            size_t hi_ix = (size_t)(m*BB+row)*HH + u;
            float hp = __bfloat162float(g_h0_hi[p][hi_ix]) + __bfloat162float(g_h0_lo[p][hi_ix]);
            float h = (1.f-z)*n + z*hp;
            bf16 hhi, hlo; splitb(h, hhi, hlo);
            g_h0_hi[q][hi_ix] = hhi; g_h0_lo[q][hi_ix] = hlo;
        }
    }
}

// ---------- layer1 fused: gx1 + gh1 + gates, dynamic smem ----------
__global__ void __launch_bounds__(256) k_l1(const float* __restrict__ bih1,
                                            const float* __restrict__ bhh1, int p) {
    const int m = blockIdx.z, rb = blockIdx.x, ub = blockIdx.y, q = p^1;
    extern __shared__ __align__(16) bf16 sm1[];
    bf16* As = sm1; bf16* Ws = sm1 + 4*64*KP;
    const bf16* Ap[4] = { g_h0_hi[q] + m*BB*HH, g_h0_lo[q] + m*BB*HH,
                          g_h1_hi[p] + m*BB*HH, g_h1_lo[p] + m*BB*HH };
    const bf16* Wp[4] = { g_wih1_hi + m*G3*HH, g_wih1_lo + m*G3*HH,
                          g_whh1_hi + m*G3*HH, g_whh1_lo + m*G3*HH };
    const int tid = threadIdx.x, lane = tid & 31, wid = tid >> 5;
    const int wm = wid >> 1, wn = wid & 1, gq = lane >> 2, tg = lane & 3;
    float acc[2][3][2][4];
#pragma unroll
    for (int a = 0; a < 2; a++)
#pragma unroll
    for (int g = 0; g < 3; g++)
#pragma unroll
    for (int b = 0; b < 2; b++)
#pragma unroll
    for (int e = 0; e < 4; e++) acc[a][g][b][e] = 0.f;

    for (int kc = 0; kc < 4; kc++) {
        const int k0 = kc * 64;
        for (int idx = tid; idx < 2048; idx += 256) {   // 4 tiles x 64 x 8
            int t = idx >> 9, rem = idx & 511, r = rem >> 3, c = rem & 7;
            ((uint4*)As)[t*64*9 + r*9 + c] = ((const uint4*)(Ap[t] + (size_t)(rb*64+r)*HH + k0))[c];
        }
        for (int idx = tid; idx < 3072; idx += 256) {   // 12 tiles ((mat*2+hl)*3+g) x 32 x 8
            int t = idx >> 8, rem = idx & 255, r = rem >> 3, c = rem & 7;
            int mh = t / 3, g = t % 3;
            ((uint4*)Ws)[t*32*9 + r*9 + c] =
                ((const uint4*)(Wp[mh] + (size_t)(g*HH + ub*32 + r)*HH + k0))[c];
        }
        __syncthreads();
#pragma unroll
        for (int ks = 0; ks < 4; ks++) {
            const int kk = ks * 16;
#pragma unroll
            for (int mat = 0; mat < 2; mat++) {
                uint32_t afr[2][4];
#pragma unroll
                for (int hl = 0; hl < 2; hl++) {
                    const bf16* at = As + ((mat*2+hl)*64 + wm*16 + gq)*KP + kk + tg*2;
                    afr[hl][0] = *(const uint32_t*)at;
                    afr[hl][1] = *(const uint32_t*)(at + 8*KP);
                    afr[hl][2] = *(const uint32_t*)(at + 8);
                    afr[hl][3] = *(const uint32_t*)(at + 8*KP + 8);
                }
#pragma unroll
                for (int g = 0; g < 3; g++) {
                    uint32_t bfr[2][2][2];
#pragma unroll
                    for (int hl = 0; hl < 2; hl++)
#pragma unroll
                        for (int nf = 0; nf < 2; nf++) {
                            const bf16* wt = Ws + (((mat*2+hl)*3+g)*32 + wn*16+nf*8+gq)*KP + kk + tg*2;
                            bfr[hl][nf][0] = *(const uint32_t*)wt;
                            bfr[hl][nf][1] = *(const uint32_t*)(wt + 8);
                        }
#pragma unroll
                    for (int nf = 0; nf < 2; nf++) {
                        mma16816(acc[mat][g][nf], afr[0], bfr[0][nf]);
                        mma16816(acc[mat][g][nf], afr[0], bfr[1][nf]);
                        mma16816(acc[mat][g][nf], afr[1], bfr[0][nf]);
                    }
                }
            }
        }
        __syncthreads();
    }
    const float* bi = bih1 + m*G3; const float* bh = bhh1 + m*G3;
#pragma unroll
    for (int e = 0; e < 2; e++) {
        int row = rb*64 + wm*16 + gq + e*8;
#pragma unroll
        for (int nf = 0; nf < 2; nf++)
#pragma unroll
        for (int cc = 0; cc < 2; cc++) {
            int u = ub*32 + wn*16 + nf*8 + tg*2 + cc;
            int ec = e*2+cc;
            float r = sigf(acc[0][0][nf][ec] + bi[u]      + acc[1][0][nf][ec] + bh[u]);
            float z = sigf(acc[0][1][nf][ec] + bi[HH+u]   + acc[1][1][nf][ec] + bh[HH+u]);
            float n = tanhf(acc[0][2][nf][ec] + bi[2*HH+u] + r*(acc[1][2][nf][ec] + bh[2*HH+u]));
            size_t hix = (size_t)(m*BB+row)*HH + u;
            float hp = __bfloat162float(g_h1_hi[p][hix]) + __bfloat162float(g_h1_lo[p][hix]);
            float h = (1.f-z)*n + z*hp;
            bf16 hhi, hlo; splitb(h, hhi, hlo);
            g_h1_hi[q][hix] = hhi; g_h1_lo[q][hix] = hlo;
            g_h1f[hix] = h;
        }
    }
}

// ---------- delta + cumsum + output ----------
__global__ void k_delta(const float* __restrict__ ow, const float* __restrict__ ob,
                        float* __restrict__ out, int t) {
    int warp = (blockIdx.x * blockDim.x + threadIdx.x) >> 5;
    int lane = threadIdx.x & 31;
    if (warp >= MM*BB) return;
    int m = warp / BB, b = warp - m*BB;
    const float* h = g_h1f + (size_t)warp * HH;
    float a0 = 0.f, a1 = 0.f;
    for (int k = lane; k < HH; k += 32) {
        float hv = h[k];
        a0 += hv * __ldg(&ow[(m*2+0)*HH + k]);
        a1 += hv * __ldg(&ow[(m*2+1)*HH + k]);
    }
#pragma unroll
    for (int o = 16; o; o >>= 1) {
        a0 += __shfl_xor_sync(0xffffffffu, a0, o);
        a1 += __shfl_xor_sync(0xffffffffu, a1, o);
    }
    if (lane == 0) {
        a0 += ob[m*2+0]; a1 += ob[m*2+1];
        g_delta[warp*2+0] = a0; g_delta[warp*2+1] = a1;
        float c0 = g_cum[warp*2+0] + a0, c1 = g_cum[warp*2+1] + a1;
        g_cum[warp*2+0] = c0; g_cum[warp*2+1] = c1;
        size_t oo = (((size_t)b*MM + m)*TT + t)*2;
        out[oo] = c0; out[oo+1] = c1;
    }
}

extern "C" void kernel_launch(void* const* d_in, const int* in_sizes, int n_in,
                              void* d_out, int out_size) {
    const float* ctx  = (const float*)d_in[0];
    const float* w1   = (const float*)d_in[1];
    const float* b1   = (const float*)d_in[2];
    const float* w2   = (const float*)d_in[3];
    const float* b2   = (const float*)d_in[4];
    const float* wih0 = (const float*)d_in[5];
    const float* bih0 = (const float*)d_in[7];
    const float* bhh0 = (const float*)d_in[8];
    const float* bih1 = (const float*)d_in[11];
    const float* bhh1 = (const float*)d_in[12];
    const float* ow   = (const float*)d_in[13];
    const float* ob   = (const float*)d_in[14];
    float* out = (float*)d_out;
    float* probs = out + (size_t)BB*MM*TT*2;

    const int SM_L1 = (4*64 + 12*32) * KP * (int)sizeof(bf16);   // 92160
    cudaFuncSetAttribute(k_l1, cudaFuncAttributeMaxDynamicSharedMemorySize, SM_L1);

    k_prep_ctx<<<(BB*FF)/256, 256>>>(ctx);
    k_prep_w<<<(4*MM*G3*HH)/256, 256>>>((const float*)d_in[6], (const float*)d_in[9],
                                        (const float*)d_in[10], wih0);
    k_prep_zero<<<96, 256>>>();
    k_modeprobs<<<256, 128>>>(ctx, w1, b1, w2, b2, probs);

    dim3 g0(BB/64, G3/32, MM);
    k_gx0<<<g0, 128>>>();

    dim3 gl(BB/64, HH/32, MM);
    for (int t = 0; t < TT; t++) {
        int p = t & 1;
        k_l0<<<gl, 256>>>(wih0, bih0, bhh0, p);
        k_l1<<<gl, 256, SM_L1>>>(bih1, bhh1, p);
        k_delta<<<(MM*BB*32+127)/128, 128>>>(ow, ob, out, t);
    }
}

// round 4
// speedup vs baseline: 1.2312x; 1.0613x over previous
#include <cuda_runtime.h>
#include <cuda_bf16.h>
#include <stdint.h>
#include <math.h>

#define BB 4096
#define FF 256
#define HH 256
#define MM 3
#define TT 30
#define G3 768
#define IN0 258
#define KP 72
#define KP2 40

typedef __nv_bfloat16 bf16;

__device__ bf16 g_ctx_hi[BB*FF], g_ctx_lo[BB*FF];
__device__ bf16 g_h0_hi[2][MM*BB*HH], g_h0_lo[2][MM*BB*HH];
__device__ bf16 g_h1_hi[2][MM*BB*HH], g_h1_lo[2][MM*BB*HH];
__device__ bf16 g_whh0_hi[MM*G3*HH], g_whh0_lo[MM*G3*HH];
__device__ bf16 g_wih1_hi[MM*G3*HH], g_wih1_lo[MM*G3*HH];
__device__ bf16 g_whh1_hi[MM*G3*HH], g_whh1_lo[MM*G3*HH];
__device__ bf16 g_wc_hi[MM*G3*HH],   g_wc_lo[MM*G3*HH];
__device__ float g_gx0[(size_t)MM*BB*G3];   // includes b_ih0
__device__ float g_wp0[MM*G3*2];            // w_ih0[:, :, 0:2] packed
__device__ float g_h1f[MM*BB*HH];
__device__ float g_delta[MM*BB*2], g_cum[MM*BB*2];

__device__ __forceinline__ void mma16816(float* d, const uint32_t* a, const uint32_t* b) {
    asm volatile(
        "mma.sync.aligned.m16n8k16.row.col.f32.bf16.bf16.f32 "
        "{%0,%1,%2,%3}, {%4,%5,%6,%7}, {%8,%9}, {%0,%1,%2,%3};\n"
        : "+f"(d[0]), "+f"(d[1]), "+f"(d[2]), "+f"(d[3])
        : "r"(a[0]), "r"(a[1]), "r"(a[2]), "r"(a[3]), "r"(b[0]), "r"(b[1]));
}
__device__ __forceinline__ void ldsm4(uint32_t* r, const bf16* p) {
    uint32_t a = (uint32_t)__cvta_generic_to_shared(p);
    asm volatile("ldmatrix.sync.aligned.m8n8.x4.shared.b16 {%0,%1,%2,%3}, [%4];\n"
                 : "=r"(r[0]), "=r"(r[1]), "=r"(r[2]), "=r"(r[3]) : "r"(a));
}
__device__ __forceinline__ void cpa(bf16* s, const bf16* g) {
    uint32_t sa = (uint32_t)__cvta_generic_to_shared(s);
    asm volatile("cp.async.cg.shared.global [%0], [%1], 16;\n" :: "r"(sa), "l"(g));
}
#define CP_COMMIT asm volatile("cp.async.commit_group;\n" ::: "memory")
#define CP_WAIT1  asm volatile("cp.async.wait_group 1;\n" ::: "memory")
#define CP_WAIT0  asm volatile("cp.async.wait_group 0;\n" ::: "memory")

__device__ __forceinline__ void splitb(float v, bf16& hi, bf16& lo) {
    hi = __float2bfloat16(v);
    lo = __float2bfloat16(v - __bfloat162float(hi));
}
__device__ __forceinline__ float sigf(float x) { return 1.f/(1.f+expf(-x)); }

// ---------- prep ----------
__global__ void k_prep_ctx(const float* __restrict__ ctx) {
    int i = blockIdx.x * blockDim.x + threadIdx.x;
    if (i >= BB * FF) return;
    bf16 hi, lo; splitb(ctx[i], hi, lo);
    g_ctx_hi[i] = hi; g_ctx_lo[i] = lo;
#pragma unroll
    for (int m = 0; m < MM; m++) {
        int o = m * BB * HH + i;
        g_h0_hi[0][o] = hi; g_h0_lo[0][o] = lo;
        g_h1_hi[0][o] = hi; g_h1_lo[0][o] = lo;
    }
}
__global__ void k_prep_w(const float* __restrict__ whh0, const float* __restrict__ wih1,
                         const float* __restrict__ whh1, const float* __restrict__ wih0) {
    const int n1 = MM * G3 * HH;
    int i = blockIdx.x * blockDim.x + threadIdx.x;
    if (i >= 4 * n1) return;
    int a = i / n1, e = i - a * n1;
    float v;
    if (a == 3) {
        int m = e / (G3 * HH), r = (e - m * G3 * HH) / HH, c = e % HH;
        v = wih0[((size_t)m * G3 + r) * IN0 + 2 + c];
    } else v = (a == 0 ? whh0 : (a == 1 ? wih1 : whh1))[e];
    bf16 hi, lo; splitb(v, hi, lo);
    if      (a == 0) { g_whh0_hi[e] = hi; g_whh0_lo[e] = lo; }
    else if (a == 1) { g_wih1_hi[e] = hi; g_wih1_lo[e] = lo; }
    else if (a == 2) { g_whh1_hi[e] = hi; g_whh1_lo[e] = lo; }
    else             { g_wc_hi[e]   = hi; g_wc_lo[e]   = lo; }
}
__global__ void k_prep_misc(const float* __restrict__ wih0) {
    int i = blockIdx.x * blockDim.x + threadIdx.x;
    if (i < MM * BB * 2) { g_delta[i] = 0.f; g_cum[i] = 0.f; }
    if (i < MM * G3) {
        g_wp0[i*2+0] = wih0[(size_t)i*IN0 + 0];
        g_wp0[i*2+1] = wih0[(size_t)i*IN0 + 1];
    }
}

// ---------- mode probs ----------
__global__ void k_modeprobs(const float* __restrict__ ctx,
                            const float* __restrict__ w1, const float* __restrict__ b1,
                            const float* __restrict__ w2, const float* __restrict__ b2,
                            float* __restrict__ probs) {
    int gw = (blockIdx.x * blockDim.x + threadIdx.x) >> 5;
    int lane = threadIdx.x & 31;
    int b0 = gw * 4;
    if (b0 >= BB) return;
    int u0 = lane * 2, u1 = u0 + 1;
    float acc[4][2];
#pragma unroll
    for (int r = 0; r < 4; r++) { acc[r][0] = 0.f; acc[r][1] = 0.f; }
    for (int k = 0; k < FF; k++) {
        float wa = __ldg(&w1[u0*FF+k]), wb = __ldg(&w1[u1*FF+k]);
#pragma unroll
        for (int r = 0; r < 4; r++) {
            float c = __ldg(&ctx[(size_t)(b0+r)*FF+k]);
            acc[r][0] += c*wa; acc[r][1] += c*wb;
        }
    }
#pragma unroll
    for (int r = 0; r < 4; r++) {
        float h0v = fmaxf(acc[r][0] + b1[u0], 0.f);
        float h1v = fmaxf(acc[r][1] + b1[u1], 0.f);
        float lg[3];
#pragma unroll
        for (int m = 0; m < 3; m++) {
            float p = h0v*w2[m*64+u0] + h1v*w2[m*64+u1];
#pragma unroll
            for (int o = 16; o; o >>= 1) p += __shfl_xor_sync(0xffffffffu, p, o);
            lg[m] = p + b2[m];
        }
        if (lane == 0) {
            float mx = fmaxf(lg[0], fmaxf(lg[1], lg[2]));
            float e0 = expf(lg[0]-mx), e1 = expf(lg[1]-mx), e2 = expf(lg[2]-mx);
            float s = e0+e1+e2;
            probs[(size_t)(b0+r)*MM+0] = e0/s;
            probs[(size_t)(b0+r)*MM+1] = e1/s;
            probs[(size_t)(b0+r)*MM+2] = e2/s;
        }
    }
}

// ---------- gx0 = ctx @ wc^T + b_ih0 (once) ----------
__global__ void __launch_bounds__(128) k_gx0(const float* __restrict__ bih0) {
    const int m = blockIdx.z, rb = blockIdx.x, ub = blockIdx.y;
    __shared__ __align__(16) bf16 sm[(2*64 + 2*32) * KP];
    bf16* As = sm; bf16* Ws = sm + 2*64*KP;
    const bf16* Ap[2] = { g_ctx_hi, g_ctx_lo };
    const bf16* Wp[2] = { g_wc_hi + m*G3*HH, g_wc_lo + m*G3*HH };
    const int tid = threadIdx.x, lane = tid & 31, wid = tid >> 5;
    const int wm = wid & 1, wn = wid >> 1, gq = lane >> 2, tg = lane & 3;
    float acc[2][2][4];
#pragma unroll
    for (int a = 0; a < 2; a++)
#pragma unroll
    for (int b = 0; b < 2; b++)
#pragma unroll
    for (int e = 0; e < 4; e++) acc[a][b][e] = 0.f;
    for (int kc = 0; kc < 4; kc++) {
        const int k0 = kc * 64;
        for (int idx = tid; idx < 1024; idx += 128) {
            int t = idx >> 9, rem = idx & 511, r = rem >> 3, c = rem & 7;
            ((uint4*)As)[t*64*9 + r*9 + c] = ((const uint4*)(Ap[t] + (size_t)(rb*64+r)*HH + k0))[c];
        }
        for (int idx = tid; idx < 512; idx += 128) {
            int t = idx >> 8, rem = idx & 255, r = rem >> 3, c = rem & 7;
            ((uint4*)Ws)[t*32*9 + r*9 + c] = ((const uint4*)(Wp[t] + (size_t)(ub*32+r)*HH + k0))[c];
        }
        __syncthreads();
#pragma unroll
        for (int ks = 0; ks < 4; ks++) {
            const int kk = ks * 16;
            uint32_t afr[2][2][4];
#pragma unroll
            for (int hl = 0; hl < 2; hl++)
#pragma unroll
                for (int mf = 0; mf < 2; mf++) {
                    const bf16* at = As + hl*64*KP + (wm*32+mf*16+gq)*KP + kk + tg*2;
                    afr[hl][mf][0] = *(const uint32_t*)at;
                    afr[hl][mf][1] = *(const uint32_t*)(at + 8*KP);
                    afr[hl][mf][2] = *(const uint32_t*)(at + 8);
                    afr[hl][mf][3] = *(const uint32_t*)(at + 8*KP + 8);
                }
            uint32_t bfr[2][2][2];
#pragma unroll
            for (int hl = 0; hl < 2; hl++)
#pragma unroll
                for (int nf = 0; nf < 2; nf++) {
                    const bf16* wt = Ws + hl*32*KP + (wn*16+nf*8+gq)*KP + kk + tg*2;
                    bfr[hl][nf][0] = *(const uint32_t*)wt;
                    bfr[hl][nf][1] = *(const uint32_t*)(wt + 8);
                }
#pragma unroll
            for (int mf = 0; mf < 2; mf++)
#pragma unroll
                for (int nf = 0; nf < 2; nf++) {
                    mma16816(acc[mf][nf], afr[0][mf], bfr[0][nf]);
                    mma16816(acc[mf][nf], afr[0][mf], bfr[1][nf]);
                    mma16816(acc[mf][nf], afr[1][mf], bfr[0][nf]);
                }
        }
        __syncthreads();
    }
#pragma unroll
    for (int mf = 0; mf < 2; mf++)
#pragma unroll
    for (int e = 0; e < 2; e++) {
        int row = rb*64 + wm*32 + mf*16 + gq + e*8;
#pragma unroll
        for (int nf = 0; nf < 2; nf++)
#pragma unroll
        for (int cc = 0; cc < 2; cc++) {
            int col = ub*32 + wn*16 + nf*8 + tg*2 + cc;
            g_gx0[((size_t)m*BB+row)*G3 + col] = acc[mf][nf][e*2+cc] + bih0[m*G3+col];
        }
    }
}

// ---------- layer0 fused (pipelined, ldmatrix) ----------
__global__ void __launch_bounds__(256, 2) k_l0(const float* __restrict__ bhh0, int p) {
    const int m = blockIdx.z, rb = blockIdx.x, ub = blockIdx.y, q = p^1;
    extern __shared__ __align__(16) bf16 sm0[];
    bf16* As = sm0;                      // 2 stages x 2 tiles x 64 x KP2
    bf16* Ws = sm0 + 2*2*64*KP2;         // 2 stages x 6 tiles x 32 x KP2
    const bf16* Ap[2] = { g_h0_hi[p] + m*BB*HH, g_h0_lo[p] + m*BB*HH };
    const bf16* Wp[2] = { g_whh0_hi + m*G3*HH, g_whh0_lo + m*G3*HH };
    const int tid = threadIdx.x, lane = tid & 31, wid = tid >> 5;
    const int wm = wid >> 1, wn = wid & 1, gq = lane >> 2, tg = lane & 3;
    const int ar = lane & 15, ac = (lane >> 4) * 8;                 // A ldsm lane map
    const int br = ((lane >> 4) & 1) * 8 + (lane & 7), bc = ((lane >> 3) & 1) * 8; // B ldsm

    float acc[3][2][4];
#pragma unroll
    for (int g = 0; g < 3; g++)
#pragma unroll
    for (int b = 0; b < 2; b++)
#pragma unroll
    for (int e = 0; e < 4; e++) acc[g][b][e] = 0.f;

    auto load = [&](int s, int c) {
        for (int i = tid; i < 512; i += 256) {   // A: 2 x 64 x 4 chunks
            int t = i >> 8, rem = i & 255, r = rem >> 2, ch = rem & 3;
            cpa(As + ((s*2 + t)*64 + r)*KP2 + ch*8,
                Ap[t] + (size_t)(rb*64 + r)*HH + c*32 + ch*8);
        }
        for (int i = tid; i < 768; i += 256) {   // W: 6 x 32 x 4
            int t = i >> 7, rem = i & 127, r = rem >> 2, ch = rem & 3;
            int hl = t / 3, g = t % 3;
            cpa(Ws + ((s*6 + t)*32 + r)*KP2 + ch*8,
                Wp[hl] + (size_t)(g*HH + ub*32 + r)*HH + c*32 + ch*8);
        }
    };

    load(0, 0); CP_COMMIT;
    for (int c = 0; c < 8; c++) {
        if (c + 1 < 8) { load((c+1)&1, c+1); CP_COMMIT; CP_WAIT1; }
        else CP_WAIT0;
        __syncthreads();
        const int s = c & 1;
#pragma unroll
        for (int ks = 0; ks < 2; ks++) {
            const int kk = ks * 16;
            uint32_t afr[2][4];
#pragma unroll
            for (int hl = 0; hl < 2; hl++)
                ldsm4(afr[hl], As + ((s*2 + hl)*64 + wm*16 + ar)*KP2 + kk + ac);
#pragma unroll
            for (int g = 0; g < 3; g++) {
                uint32_t bfr[2][4];
#pragma unroll
                for (int hl = 0; hl < 2; hl++)
                    ldsm4(bfr[hl], Ws + ((s*6 + hl*3 + g)*32 + wn*16 + br)*KP2 + kk + bc);
#pragma unroll
                for (int nf = 0; nf < 2; nf++) {
                    mma16816(acc[g][nf], afr[0], &bfr[0][nf*2]);
                    mma16816(acc[g][nf], afr[0], &bfr[1][nf*2]);
                    mma16816(acc[g][nf], afr[1], &bfr[0][nf*2]);
                }
            }
        }
        __syncthreads();
    }

    const float* bh = bhh0 + m*G3;
#pragma unroll
    for (int e = 0; e < 2; e++) {
        int row = rb*64 + wm*16 + gq + e*8;
        float px = g_delta[(m*BB+row)*2+0], py = g_delta[(m*BB+row)*2+1];
        size_t gxb = (size_t)(m*BB+row)*G3;
#pragma unroll
        for (int nf = 0; nf < 2; nf++)
#pragma unroll
        for (int cc = 0; cc < 2; cc++) {
            int u = ub*32 + wn*16 + nf*8 + tg*2 + cc;
            int ec = e*2+cc;
            const float* w0 = g_wp0 + (m*G3+u)*2;
            const float* w1p = g_wp0 + (m*G3+HH+u)*2;
            const float* w2p = g_wp0 + (m*G3+2*HH+u)*2;
            float xr = g_gx0[gxb+u]      + px*w0[0]  + py*w0[1];
            float xz = g_gx0[gxb+HH+u]   + px*w1p[0] + py*w1p[1];
            float xn = g_gx0[gxb+2*HH+u] + px*w2p[0] + py*w2p[1];
            float r = sigf(xr + acc[0][nf][ec] + bh[u]);
            float z = sigf(xz + acc[1][nf][ec] + bh[HH+u]);
            float n = tanhf(xn + r*(acc[2][nf][ec] + bh[2*HH+u]));
            size_t hix = (size_t)(m*BB+row)*HH + u;
            float hp = __bfloat162float(g_h0_hi[p][hix]) + __bfloat162float(g_h0_lo[p][hix]);
            float h = (1.f-z)*n + z*hp;
            bf16 hhi, hlo; splitb(h, hhi, hlo);
            g_h0_hi[q][hix] = hhi; g_h0_lo[q][hix] = hlo;
        }
    }
}

// ---------- layer1 fused (pipelined, ldmatrix) ----------
__global__ void __launch_bounds__(256, 2) k_l1(const float* __restrict__ bih1,
                                               const float* __restrict__ bhh1, int p) {
    const int m = blockIdx.z, rb = blockIdx.x, ub = blockIdx.y, q = p^1;
    extern __shared__ __align__(16) bf16 sm1[];
    bf16* As = sm1;                      // 2 x 4 x 64 x KP2
    bf16* Ws = sm1 + 2*4*64*KP2;         // 2 x 12 x 32 x KP2
    const bf16* Ap[4] = { g_h0_hi[q] + m*BB*HH, g_h0_lo[q] + m*BB*HH,
                          g_h1_hi[p] + m*BB*HH, g_h1_lo[p] + m*BB*HH };
    const bf16* Wp[4] = { g_wih1_hi + m*G3*HH, g_wih1_lo + m*G3*HH,
                          g_whh1_hi + m*G3*HH, g_whh1_lo + m*G3*HH };
    const int tid = threadIdx.x, lane = tid & 31, wid = tid >> 5;
    const int wm = wid >> 1, wn = wid & 1, gq = lane >> 2, tg = lane & 3;
    const int ar = lane & 15, ac = (lane >> 4) * 8;
    const int br = ((lane >> 4) & 1) * 8 + (lane & 7), bc = ((lane >> 3) & 1) * 8;

    float acc[2][3][2][4];
#pragma unroll
    for (int a = 0; a < 2; a++)
#pragma unroll
    for (int g = 0; g < 3; g++)
#pragma unroll
    for (int b = 0; b < 2; b++)
#pragma unroll
    for (int e = 0; e < 4; e++) acc[a][g][b][e] = 0.f;

    auto load = [&](int s, int c) {
        for (int i = tid; i < 1024; i += 256) {   // A: 4 x 64 x 4
            int t = i >> 8, rem = i & 255, r = rem >> 2, ch = rem & 3;
            cpa(As + ((s*4 + t)*64 + r)*KP2 + ch*8,
                Ap[t] + (size_t)(rb*64 + r)*HH + c*32 + ch*8);
        }
        for (int i = tid; i < 1536; i += 256) {   // W: 12 x 32 x 4
            int t = i >> 7, rem = i & 127, r = rem >> 2, ch = rem & 3;
            int mh = t / 3, g = t % 3;
            cpa(Ws + ((s*12 + t)*32 + r)*KP2 + ch*8,
                Wp[mh] + (size_t)(g*HH + ub*32 + r)*HH + c*32 + ch*8);
        }
    };

    load(0, 0); CP_COMMIT;
    for (int c = 0; c < 8; c++) {
        if (c + 1 < 8) { load((c+1)&1, c+1); CP_COMMIT; CP_WAIT1; }
        else CP_WAIT0;
        __syncthreads();
        const int s = c & 1;
#pragma unroll
        for (int ks = 0; ks < 2; ks++) {
            const int kk = ks * 16;
#pragma unroll
            for (int mat = 0; mat < 2; mat++) {
                uint32_t afr[2][4];
#pragma unroll
                for (int hl = 0; hl < 2; hl++)
                    ldsm4(afr[hl], As + ((s*4 + mat*2 + hl)*64 + wm*16 + ar)*KP2 + kk + ac);
#pragma unroll
                for (int g = 0; g < 3; g++) {
                    uint32_t bfr[2][4];
#pragma unroll
                    for (int hl = 0; hl < 2; hl++)
                        ldsm4(bfr[hl], Ws + ((s*12 + (mat*2+hl)*3 + g)*32 + wn*16 + br)*KP2 + kk + bc);
#pragma unroll
                    for (int nf = 0; nf < 2; nf++) {
                        mma16816(acc[mat][g][nf], afr[0], &bfr[0][nf*2]);
                        mma16816(acc[mat][g][nf], afr[0], &bfr[1][nf*2]);
                        mma16816(acc[mat][g][nf], afr[1], &bfr[0][nf*2]);
                    }
                }
            }
        }
        __syncthreads();
    }

    const float* bi = bih1 + m*G3; const float* bh = bhh1 + m*G3;
#pragma unroll
    for (int e = 0; e < 2; e++) {
        int row = rb*64 + wm*16 + gq + e*8;
#pragma unroll
        for (int nf = 0; nf < 2; nf++)
#pragma unroll
        for (int cc = 0; cc < 2; cc++) {
            int u = ub*32 + wn*16 + nf*8 + tg*2 + cc;
            int ec = e*2+cc;
            float r = sigf(acc[0][0][nf][ec] + bi[u]      + acc[1][0][nf][ec] + bh[u]);
            float z = sigf(acc[0][1][nf][ec] + bi[HH+u]   + acc[1][1][nf][ec] + bh[HH+u]);
            float n = tanhf(acc[0][2][nf][ec] + bi[2*HH+u] + r*(acc[1][2][nf][ec] + bh[2*HH+u]));
            size_t hix = (size_t)(m*BB+row)*HH + u;
            float hp = __bfloat162float(g_h1_hi[p][hix]) + __bfloat162float(g_h1_lo[p][hix]);
            float h = (1.f-z)*n + z*hp;
            bf16 hhi, hlo; splitb(h, hhi, hlo);
            g_h1_hi[q][hix] = hhi; g_h1_lo[q][hix] = hlo;
            g_h1f[hix] = h;
        }
    }
}

// ---------- delta + cumsum + output ----------
__global__ void k_delta(const float* __restrict__ ow, const float* __restrict__ ob,
                        float* __restrict__ out, int t) {
    int warp = (blockIdx.x * blockDim.x + threadIdx.x) >> 5;
    int lane = threadIdx.x & 31;
    if (warp >= MM*BB) return;
    int m = warp / BB, b = warp - m*BB;
    const float* h = g_h1f + (size_t)warp * HH;
    float a0 = 0.f, a1 = 0.f;
    for (int k = lane; k < HH; k += 32) {
        float hv = h[k];
        a0 += hv * __ldg(&ow[(m*2+0)*HH + k]);
        a1 += hv * __ldg(&ow[(m*2+1)*HH + k]);
    }
#pragma unroll
    for (int o = 16; o; o >>= 1) {
        a0 += __shfl_xor_sync(0xffffffffu, a0, o);
        a1 += __shfl_xor_sync(0xffffffffu, a1, o);
    }
    if (lane == 0) {
        a0 += ob[m*2+0]; a1 += ob[m*2+1];
        g_delta[warp*2+0] = a0; g_delta[warp*2+1] = a1;
        float c0 = g_cum[warp*2+0] + a0, c1 = g_cum[warp*2+1] + a1;
        g_cum[warp*2+0] = c0; g_cum[warp*2+1] = c1;
        size_t oo = (((size_t)b*MM + m)*TT + t)*2;
        out[oo] = c0; out[oo+1] = c1;
    }
}

extern "C" void kernel_launch(void* const* d_in, const int* in_sizes, int n_in,
                              void* d_out, int out_size) {
    const float* ctx  = (const float*)d_in[0];
    const float* w1   = (const float*)d_in[1];
    const float* b1   = (const float*)d_in[2];
    const float* w2   = (const float*)d_in[3];
    const float* b2   = (const float*)d_in[4];
    const float* wih0 = (const float*)d_in[5];
    const float* bih0 = (const float*)d_in[7];
    const float* bhh0 = (const float*)d_in[8];
    const float* bih1 = (const float*)d_in[11];
    const float* bhh1 = (const float*)d_in[12];
    const float* ow   = (const float*)d_in[13];
    const float* ob   = (const float*)d_in[14];
    float* out = (float*)d_out;
    float* probs = out + (size_t)BB*MM*TT*2;

    const int SM_L0 = (2*2*64 + 2*6*32) * KP2 * (int)sizeof(bf16);   // 51200
    const int SM_L1 = (2*4*64 + 2*12*32) * KP2 * (int)sizeof(bf16);  // 102400
    cudaFuncSetAttribute(k_l0, cudaFuncAttributeMaxDynamicSharedMemorySize, SM_L0);
    cudaFuncSetAttribute(k_l1, cudaFuncAttributeMaxDynamicSharedMemorySize, SM_L1);

    k_prep_ctx<<<(BB*FF)/256, 256>>>(ctx);
    k_prep_w<<<(4*MM*G3*HH)/256, 256>>>((const float*)d_in[6], (const float*)d_in[9],
                                        (const float*)d_in[10], wih0);
    k_prep_misc<<<96, 256>>>(wih0);
    k_modeprobs<<<256, 128>>>(ctx, w1, b1, w2, b2, probs);

    dim3 g0(BB/64, G3/32, MM);
    k_gx0<<<g0, 128>>>(bih0);

    dim3 gl(BB/64, HH/32, MM);
    for (int t = 0; t < TT; t++) {
        int p = t & 1;
        k_l0<<<gl, 256, SM_L0>>>(bhh0, p);
        k_l1<<<gl, 256, SM_L1>>>(bih1, bhh1, p);
        k_delta<<<(MM*BB*32+127)/128, 128>>>(ow, ob, out, t);
    }
}

// round 5
// speedup vs baseline: 1.5387x; 1.2498x over previous
#include <cuda_runtime.h>
#include <cuda_fp16.h>
#include <stdint.h>
#include <math.h>

#define BB 4096
#define FF 256
#define HH 256
#define MM 3
#define TT 30
#define G3 768
#define IN0 258
#define KP 72
#define KP2 40

typedef __half h16;

__device__ h16 g_ctx_hi[BB*FF], g_ctx_lo[BB*FF];
__device__ h16 g_h0_hi[2][MM*BB*HH], g_h0_lo[2][MM*BB*HH];
__device__ h16 g_h1_hi[2][MM*BB*HH], g_h1_lo[2][MM*BB*HH];
__device__ h16 g_whh0[MM*G3*HH];
__device__ h16 g_wih1[MM*G3*HH];
__device__ h16 g_whh1[MM*G3*HH];
__device__ h16 g_wc[MM*G3*HH];
__device__ float g_gx0[(size_t)MM*BB*G3];   // includes b_ih0
__device__ float g_wp0[MM*G3*2];            // w_ih0[:, :, 0:2] packed
__device__ float g_h1f[MM*BB*HH];
__device__ float g_delta[MM*BB*2], g_cum[MM*BB*2];

__device__ __forceinline__ void mma16816(float* d, const uint32_t* a, const uint32_t* b) {
    asm volatile(
        "mma.sync.aligned.m16n8k16.row.col.f32.f16.f16.f32 "
        "{%0,%1,%2,%3}, {%4,%5,%6,%7}, {%8,%9}, {%0,%1,%2,%3};\n"
        : "+f"(d[0]), "+f"(d[1]), "+f"(d[2]), "+f"(d[3])
        : "r"(a[0]), "r"(a[1]), "r"(a[2]), "r"(a[3]), "r"(b[0]), "r"(b[1]));
}
__device__ __forceinline__ void ldsm4(uint32_t* r, const h16* p) {
    uint32_t a = (uint32_t)__cvta_generic_to_shared(p);
    asm volatile("ldmatrix.sync.aligned.m8n8.x4.shared.b16 {%0,%1,%2,%3}, [%4];\n"
                 : "=r"(r[0]), "=r"(r[1]), "=r"(r[2]), "=r"(r[3]) : "r"(a));
}
__device__ __forceinline__ void cpa(h16* s, const h16* g) {
    uint32_t sa = (uint32_t)__cvta_generic_to_shared(s);
    asm volatile("cp.async.cg.shared.global [%0], [%1], 16;\n" :: "r"(sa), "l"(g));
}
#define CP_COMMIT asm volatile("cp.async.commit_group;\n" ::: "memory")
#define CP_WAIT1  asm volatile("cp.async.wait_group 1;\n" ::: "memory")
#define CP_WAIT0  asm volatile("cp.async.wait_group 0;\n" ::: "memory")

__device__ __forceinline__ void splith(float v, h16& hi, h16& lo) {
    hi = __float2half_rn(v);
    lo = __float2half_rn(v - __half2float(hi));
}
__device__ __forceinline__ float sigf(float x) { return 1.f/(1.f+expf(-x)); }

// ---------- single prep kernel ----------
__global__ void k_prep_all(const float* __restrict__ ctx, const float* __restrict__ whh0,
                           const float* __restrict__ wih1, const float* __restrict__ whh1,
                           const float* __restrict__ wih0) {
    const int n1 = MM*G3*HH;
    const int N0 = BB*FF, N1 = N0 + 4*n1, N2 = N1 + MM*G3, N3 = N2 + MM*BB*2;
    for (int i = blockIdx.x*blockDim.x + threadIdx.x; i < N3; i += gridDim.x*blockDim.x) {
        if (i < N0) {
            h16 hi, lo; splith(ctx[i], hi, lo);
            g_ctx_hi[i] = hi; g_ctx_lo[i] = lo;
#pragma unroll
            for (int m = 0; m < MM; m++) {
                int o = m*BB*HH + i;
                g_h0_hi[0][o] = hi; g_h0_lo[0][o] = lo;
                g_h1_hi[0][o] = hi; g_h1_lo[0][o] = lo;
            }
        } else if (i < N1) {
            int j = i - N0, a = j / n1, e = j - a*n1;
            float v;
            if (a == 3) {
                int m = e / (G3*HH), r = (e - m*G3*HH) / HH, c = e % HH;
                v = wih0[((size_t)m*G3 + r)*IN0 + 2 + c];
            } else v = (a == 0 ? whh0 : (a == 1 ? wih1 : whh1))[e];
            h16 w = __float2half_rn(v);
            if      (a == 0) g_whh0[e] = w;
            else if (a == 1) g_wih1[e] = w;
            else if (a == 2) g_whh1[e] = w;
            else             g_wc[e]   = w;
        } else if (i < N2) {
            int j = i - N1;
            g_wp0[j*2+0] = wih0[(size_t)j*IN0 + 0];
            g_wp0[j*2+1] = wih0[(size_t)j*IN0 + 1];
        } else {
            int j = i - N2;
            g_delta[j] = 0.f; g_cum[j] = 0.f;
        }
    }
}

// ---------- gx0 = ctx @ wc^T + b_ih0 (once) ----------
__global__ void __launch_bounds__(128) k_gx0(const float* __restrict__ bih0) {
    const int m = blockIdx.z, rb = blockIdx.x, ub = blockIdx.y;
    __shared__ __align__(16) h16 sm[(2*64 + 32) * KP];
    h16* As = sm; h16* Ws = sm + 2*64*KP;
    const h16* Ap[2] = { g_ctx_hi, g_ctx_lo };
    const h16* W = g_wc + m*G3*HH;
    const int tid = threadIdx.x, lane = tid & 31, wid = tid >> 5;
    const int wm = wid & 1, wn = wid >> 1, gq = lane >> 2, tg = lane & 3;
    float acc[2][2][4];
#pragma unroll
    for (int a = 0; a < 2; a++)
#pragma unroll
    for (int b = 0; b < 2; b++)
#pragma unroll
    for (int e = 0; e < 4; e++) acc[a][b][e] = 0.f;
    for (int kc = 0; kc < 4; kc++) {
        const int k0 = kc * 64;
        for (int idx = tid; idx < 1024; idx += 128) {
            int t = idx >> 9, rem = idx & 511, r = rem >> 3, c = rem & 7;
            ((uint4*)As)[t*64*9 + r*9 + c] = ((const uint4*)(Ap[t] + (size_t)(rb*64+r)*HH + k0))[c];
        }
        for (int idx = tid; idx < 256; idx += 128) {
            int r = idx >> 3, c = idx & 7;
            ((uint4*)Ws)[r*9 + c] = ((const uint4*)(W + (size_t)(ub*32+r)*HH + k0))[c];
        }
        __syncthreads();
#pragma unroll
        for (int ks = 0; ks < 4; ks++) {
            const int kk = ks * 16;
            uint32_t afr[2][2][4];
#pragma unroll
            for (int hl = 0; hl < 2; hl++)
#pragma unroll
                for (int mf = 0; mf < 2; mf++) {
                    const h16* at = As + hl*64*KP + (wm*32+mf*16+gq)*KP + kk + tg*2;
                    afr[hl][mf][0] = *(const uint32_t*)at;
                    afr[hl][mf][1] = *(const uint32_t*)(at + 8*KP);
                    afr[hl][mf][2] = *(const uint32_t*)(at + 8);
                    afr[hl][mf][3] = *(const uint32_t*)(at + 8*KP + 8);
                }
            uint32_t bfr[2][2];
#pragma unroll
            for (int nf = 0; nf < 2; nf++) {
                const h16* wt = Ws + (wn*16+nf*8+gq)*KP + kk + tg*2;
                bfr[nf][0] = *(const uint32_t*)wt;
                bfr[nf][1] = *(const uint32_t*)(wt + 8);
            }
#pragma unroll
            for (int mf = 0; mf < 2; mf++)
#pragma unroll
                for (int nf = 0; nf < 2; nf++) {
                    mma16816(acc[mf][nf], afr[0][mf], bfr[nf]);
                    mma16816(acc[mf][nf], afr[1][mf], bfr[nf]);
                }
        }
        __syncthreads();
    }
#pragma unroll
    for (int mf = 0; mf < 2; mf++)
#pragma unroll
    for (int e = 0; e < 2; e++) {
        int row = rb*64 + wm*32 + mf*16 + gq + e*8;
#pragma unroll
        for (int nf = 0; nf < 2; nf++)
#pragma unroll
        for (int cc = 0; cc < 2; cc++) {
            int col = ub*32 + wn*16 + nf*8 + tg*2 + cc;
            g_gx0[((size_t)m*BB+row)*G3 + col] = acc[mf][nf][e*2+cc] + bih0[m*G3+col];
        }
    }
}

// ---------- layer0 fused (pipelined, ldmatrix, fp16x2) ----------
__global__ void __launch_bounds__(256, 2) k_l0(const float* __restrict__ bhh0, int p) {
    const int m = blockIdx.z, rb = blockIdx.x, ub = blockIdx.y, q = p^1;
    extern __shared__ __align__(16) h16 sm0[];
    h16* As = sm0;                      // 2 stages x 2 tiles x 64 x KP2
    h16* Ws = sm0 + 2*2*64*KP2;         // 2 stages x 3 tiles x 32 x KP2
    const h16* Ap[2] = { g_h0_hi[p] + m*BB*HH, g_h0_lo[p] + m*BB*HH };
    const h16* W = g_whh0 + m*G3*HH;
    const int tid = threadIdx.x, lane = tid & 31, wid = tid >> 5;
    const int wm = wid >> 1, wn = wid & 1, gq = lane >> 2, tg = lane & 3;
    const int ar = lane & 15, ac = (lane >> 4) * 8;
    const int br = ((lane >> 4) & 1) * 8 + (lane & 7), bc = ((lane >> 3) & 1) * 8;

    float acc[3][2][4];
#pragma unroll
    for (int g = 0; g < 3; g++)
#pragma unroll
    for (int b = 0; b < 2; b++)
#pragma unroll
    for (int e = 0; e < 4; e++) acc[g][b][e] = 0.f;

    auto load = [&](int s, int c) {
        for (int i = tid; i < 512; i += 256) {   // A: 2 x 64 x 4 chunks
            int t = i >> 8, rem = i & 255, r = rem >> 2, ch = rem & 3;
            cpa(As + ((s*2 + t)*64 + r)*KP2 + ch*8,
                Ap[t] + (size_t)(rb*64 + r)*HH + c*32 + ch*8);
        }
        for (int i = tid; i < 384; i += 256) {   // W: 3 x 32 x 4
            int g = i >> 7, rem = i & 127, r = rem >> 2, ch = rem & 3;
            cpa(Ws + ((s*3 + g)*32 + r)*KP2 + ch*8,
                W + (size_t)(g*HH + ub*32 + r)*HH + c*32 + ch*8);
        }
    };

    load(0, 0); CP_COMMIT;
    for (int c = 0; c < 8; c++) {
        if (c + 1 < 8) { load((c+1)&1, c+1); CP_COMMIT; CP_WAIT1; }
        else CP_WAIT0;
        __syncthreads();
        const int s = c & 1;
#pragma unroll
        for (int ks = 0; ks < 2; ks++) {
            const int kk = ks * 16;
            uint32_t afr[2][4];
#pragma unroll
            for (int hl = 0; hl < 2; hl++)
                ldsm4(afr[hl], As + ((s*2 + hl)*64 + wm*16 + ar)*KP2 + kk + ac);
#pragma unroll
            for (int g = 0; g < 3; g++) {
                uint32_t bfr[4];
                ldsm4(bfr, Ws + ((s*3 + g)*32 + wn*16 + br)*KP2 + kk + bc);
#pragma unroll
                for (int nf = 0; nf < 2; nf++) {
                    mma16816(acc[g][nf], afr[0], &bfr[nf*2]);
                    mma16816(acc[g][nf], afr[1], &bfr[nf*2]);
                }
            }
        }
        __syncthreads();
    }

    const float* bh = bhh0 + m*G3;
#pragma unroll
    for (int e = 0; e < 2; e++) {
        int row = rb*64 + wm*16 + gq + e*8;
        float px = g_delta[(m*BB+row)*2+0], py = g_delta[(m*BB+row)*2+1];
        size_t gxb = (size_t)(m*BB+row)*G3;
#pragma unroll
        for (int nf = 0; nf < 2; nf++)
#pragma unroll
        for (int cc = 0; cc < 2; cc++) {
            int u = ub*32 + wn*16 + nf*8 + tg*2 + cc;
            int ec = e*2+cc;
            const float* w0 = g_wp0 + (m*G3+u)*2;
            const float* w1p = g_wp0 + (m*G3+HH+u)*2;
            const float* w2p = g_wp0 + (m*G3+2*HH+u)*2;
            float xr = g_gx0[gxb+u]      + px*w0[0]  + py*w0[1];
            float xz = g_gx0[gxb+HH+u]   + px*w1p[0] + py*w1p[1];
            float xn = g_gx0[gxb+2*HH+u] + px*w2p[0] + py*w2p[1];
            float r = sigf(xr + acc[0][nf][ec] + bh[u]);
            float z = sigf(xz + acc[1][nf][ec] + bh[HH+u]);
            float n = tanhf(xn + r*(acc[2][nf][ec] + bh[2*HH+u]));
            size_t hix = (size_t)(m*BB+row)*HH + u;
            float hp = __half2float(g_h0_hi[p][hix]) + __half2float(g_h0_lo[p][hix]);
            float h = (1.f-z)*n + z*hp;
            h16 hhi, hlo; splith(h, hhi, hlo);
            g_h0_hi[q][hix] = hhi; g_h0_lo[q][hix] = hlo;
        }
    }
}

// ---------- layer1 fused (pipelined, ldmatrix, fp16x2) ----------
__global__ void __launch_bounds__(256, 2) k_l1(const float* __restrict__ bih1,
                                               const float* __restrict__ bhh1, int p) {
    const int m = blockIdx.z, rb = blockIdx.x, ub = blockIdx.y, q = p^1;
    extern __shared__ __align__(16) h16 sm1[];
    h16* As = sm1;                      // 2 x 4 x 64 x KP2
    h16* Ws = sm1 + 2*4*64*KP2;         // 2 x 6 x 32 x KP2
    const h16* Ap[4] = { g_h0_hi[q] + m*BB*HH, g_h0_lo[q] + m*BB*HH,
                         g_h1_hi[p] + m*BB*HH, g_h1_lo[p] + m*BB*HH };
    const h16* Wp[2] = { g_wih1 + m*G3*HH, g_whh1 + m*G3*HH };
    const int tid = threadIdx.x, lane = tid & 31, wid = tid >> 5;
    const int wm = wid >> 1, wn = wid & 1, gq = lane >> 2, tg = lane & 3;
    const int ar = lane & 15, ac = (lane >> 4) * 8;
    const int br = ((lane >> 4) & 1) * 8 + (lane & 7), bc = ((lane >> 3) & 1) * 8;

    float acc[2][3][2][4];
#pragma unroll
    for (int a = 0; a < 2; a++)
#pragma unroll
    for (int g = 0; g < 3; g++)
#pragma unroll
    for (int b = 0; b < 2; b++)
#pragma unroll
    for (int e = 0; e < 4; e++) acc[a][g][b][e] = 0.f;

    auto load = [&](int s, int c) {
        for (int i = tid; i < 1024; i += 256) {   // A: 4 x 64 x 4
            int t = i >> 8, rem = i & 255, r = rem >> 2, ch = rem & 3;
            cpa(As + ((s*4 + t)*64 + r)*KP2 + ch*8,
                Ap[t] + (size_t)(rb*64 + r)*HH + c*32 + ch*8);
        }
        for (int i = tid; i < 768; i += 256) {    // W: 6 x 32 x 4
            int t = i >> 7, rem = i & 127, r = rem >> 2, ch = rem & 3;
            int mat = t / 3, g = t % 3;
            cpa(Ws + ((s*6 + t)*32 + r)*KP2 + ch*8,
                Wp[mat] + (size_t)(g*HH + ub*32 + r)*HH + c*32 + ch*8);
        }
    };

    load(0, 0); CP_COMMIT;
    for (int c = 0; c < 8; c++) {
        if (c + 1 < 8) { load((c+1)&1, c+1); CP_COMMIT; CP_WAIT1; }
        else CP_WAIT0;
        __syncthreads();
        const int s = c & 1;
#pragma unroll
        for (int ks = 0; ks < 2; ks++) {
            const int kk = ks * 16;
#pragma unroll
            for (int mat = 0; mat < 2; mat++) {
                uint32_t afr[2][4];
#pragma unroll
                for (int hl = 0; hl < 2; hl++)
                    ldsm4(afr[hl], As + ((s*4 + mat*2 + hl)*64 + wm*16 + ar)*KP2 + kk + ac);
#pragma unroll
                for (int g = 0; g < 3; g++) {
                    uint32_t bfr[4];
                    ldsm4(bfr, Ws + ((s*6 + mat*3 + g)*32 + wn*16 + br)*KP2 + kk + bc);
#pragma unroll
                    for (int nf = 0; nf < 2; nf++) {
                        mma16816(acc[mat][g][nf], afr[0], &bfr[nf*2]);
                        mma16816(acc[mat][g][nf], afr[1], &bfr[nf*2]);
                    }
                }
            }
        }
        __syncthreads();
    }

    const float* bi = bih1 + m*G3; const float* bh = bhh1 + m*G3;
#pragma unroll
    for (int e = 0; e < 2; e++) {
        int row = rb*64 + wm*16 + gq + e*8;
#pragma unroll
        for (int nf = 0; nf < 2; nf++)
#pragma unroll
        for (int cc = 0; cc < 2; cc++) {
            int u = ub*32 + wn*16 + nf*8 + tg*2 + cc;
            int ec = e*2+cc;
            float r = sigf(acc[0][0][nf][ec] + bi[u]      + acc[1][0][nf][ec] + bh[u]);
            float z = sigf(acc[0][1][nf][ec] + bi[HH+u]   + acc[1][1][nf][ec] + bh[HH+u]);
            float n = tanhf(acc[0][2][nf][ec] + bi[2*HH+u] + r*(acc[1][2][nf][ec] + bh[2*HH+u]));
            size_t hix = (size_t)(m*BB+row)*HH + u;
            float hp = __half2float(g_h1_hi[p][hix]) + __half2float(g_h1_lo[p][hix]);
            float h = (1.f-z)*n + z*hp;
            h16 hhi, hlo; splith(h, hhi, hlo);
            g_h1_hi[q][hix] = hhi; g_h1_lo[q][hix] = hlo;
            g_h1f[hix] = h;
        }
    }
}

// ---------- delta + cumsum + output ----------
__global__ void k_delta(const float* __restrict__ ow, const float* __restrict__ ob,
                        float* __restrict__ out, int t) {
    int warp = (blockIdx.x * blockDim.x + threadIdx.x) >> 5;
    int lane = threadIdx.x & 31;
    if (warp >= MM*BB) return;
    int m = warp / BB, b = warp - m*BB;
    const float* h = g_h1f + (size_t)warp * HH;
    float a0 = 0.f, a1 = 0.f;
    for (int k = lane; k < HH; k += 32) {
        float hv = h[k];
        a0 += hv * __ldg(&ow[(m*2+0)*HH + k]);
        a1 += hv * __ldg(&ow[(m*2+1)*HH + k]);
    }
#pragma unroll
    for (int o = 16; o; o >>= 1) {
        a0 += __shfl_xor_sync(0xffffffffu, a0, o);
        a1 += __shfl_xor_sync(0xffffffffu, a1, o);
    }
    if (lane == 0) {
        a0 += ob[m*2+0]; a1 += ob[m*2+1];
        g_delta[warp*2+0] = a0; g_delta[warp*2+1] = a1;
        float c0 = g_cum[warp*2+0] + a0, c1 = g_cum[warp*2+1] + a1;
        g_cum[warp*2+0] = c0; g_cum[warp*2+1] = c1;
        size_t oo = (((size_t)b*MM + m)*TT + t)*2;
        out[oo] = c0; out[oo+1] = c1;
    }
}

// ---------- mode probs ----------
__global__ void k_modeprobs(const float* __restrict__ ctx,
                            const float* __restrict__ w1, const float* __restrict__ b1,
                            const float* __restrict__ w2, const float* __restrict__ b2,
                            float* __restrict__ probs) {
    int gw = (blockIdx.x * blockDim.x + threadIdx.x) >> 5;
    int lane = threadIdx.x & 31;
    int b0 = gw * 4;
    if (b0 >= BB) return;
    int u0 = lane * 2, u1 = u0 + 1;
    float acc[4][2];
#pragma unroll
    for (int r = 0; r < 4; r++) { acc[r][0] = 0.f; acc[r][1] = 0.f; }
    for (int k = 0; k < FF; k++) {
        float wa = __ldg(&w1[u0*FF+k]), wb = __ldg(&w1[u1*FF+k]);
#pragma unroll
        for (int r = 0; r < 4; r++) {
            float c = __ldg(&ctx[(size_t)(b0+r)*FF+k]);
            acc[r][0] += c*wa; acc[r][1] += c*wb;
        }
    }
#pragma unroll
    for (int r = 0; r < 4; r++) {
        float h0v = fmaxf(acc[r][0] + b1[u0], 0.f);
        float h1v = fmaxf(acc[r][1] + b1[u1], 0.f);
        float lg[3];
#pragma unroll
        for (int m = 0; m < 3; m++) {
            float p = h0v*w2[m*64+u0] + h1v*w2[m*64+u1];
#pragma unroll
            for (int o = 16; o; o >>= 1) p += __shfl_xor_sync(0xffffffffu, p, o);
            lg[m] = p + b2[m];
        }
        if (lane == 0) {
            float mx = fmaxf(lg[0], fmaxf(lg[1], lg[2]));
            float e0 = expf(lg[0]-mx), e1 = expf(lg[1]-mx), e2 = expf(lg[2]-mx);
            float s = e0+e1+e2;
            probs[(size_t)(b0+r)*MM+0] = e0/s;
            probs[(size_t)(b0+r)*MM+1] = e1/s;
            probs[(size_t)(b0+r)*MM+2] = e2/s;
        }
    }
}

extern "C" void kernel_launch(void* const* d_in, const int* in_sizes, int n_in,
                              void* d_out, int out_size) {
    const float* ctx  = (const float*)d_in[0];
    const float* w1   = (const float*)d_in[1];
    const float* b1   = (const float*)d_in[2];
    const float* w2   = (const float*)d_in[3];
    const float* b2   = (const float*)d_in[4];
    const float* wih0 = (const float*)d_in[5];
    const float* bih0 = (const float*)d_in[7];
    const float* bhh0 = (const float*)d_in[8];
    const float* bih1 = (const float*)d_in[11];
    const float* bhh1 = (const float*)d_in[12];
    const float* ow   = (const float*)d_in[13];
    const float* ob   = (const float*)d_in[14];
    float* out = (float*)d_out;
    float* probs = out + (size_t)BB*MM*TT*2;

    const int SM_L0 = (2*2*64 + 2*3*32) * KP2 * (int)sizeof(h16);   // 35840
    const int SM_L1 = (2*4*64 + 2*6*32) * KP2 * (int)sizeof(h16);   // 71680
    cudaFuncSetAttribute(k_l0, cudaFuncAttributeMaxDynamicSharedMemorySize, SM_L0);
    cudaFuncSetAttribute(k_l1, cudaFuncAttributeMaxDynamicSharedMemorySize, SM_L1);

    const int NPREP = BB*FF + 4*MM*G3*HH + MM*G3 + MM*BB*2;
    k_prep_all<<<(NPREP+255)/256, 256>>>(ctx, (const float*)d_in[6], (const float*)d_in[9],
                                         (const float*)d_in[10], wih0);

    dim3 g0(BB/64, G3/32, MM);
    k_gx0<<<g0, 128>>>(bih0);

    dim3 gl(BB/64, HH/32, MM);
    for (int t = 0; t < TT; t++) {
        int p = t & 1;
        k_l0<<<gl, 256, SM_L0>>>(bhh0, p);
        k_l1<<<gl, 256, SM_L1>>>(bih1, bhh1, p);
        k_delta<<<(MM*BB*32+127)/128, 128>>>(ow, ob, out, t);
    }

    k_modeprobs<<<256, 128>>>(ctx, w1, b1, w2, b2, probs);
}

// round 6
// speedup vs baseline: 1.5435x; 1.0031x over previous
#include <cuda_runtime.h>
#include <cuda_fp16.h>
#include <stdint.h>
#include <math.h>

#define BB 4096
#define FF 256
#define HH 256
#define MM 3
#define TT 30
#define G3 768
#define IN0 258
#define KP 72
#define KP2 40

typedef __half h16;

__device__ h16 g_ctx_hi[BB*FF], g_ctx_lo[BB*FF];
__device__ h16 g_h0_hi[2][MM*BB*HH], g_h0_lo[2][MM*BB*HH];
__device__ h16 g_h1_hi[2][MM*BB*HH], g_h1_lo[2][MM*BB*HH];
__device__ h16 g_whh0[MM*G3*HH];
__device__ h16 g_wih1[MM*G3*HH];
__device__ h16 g_whh1[MM*G3*HH];
__device__ h16 g_wc[MM*G3*HH];
__device__ float g_gx0[(size_t)MM*BB*G3];   // includes b_ih0
__device__ float g_wp0[MM*G3*2];            // w_ih0[:, :, 0:2] packed
__device__ float g_h1f[MM*BB*HH];
__device__ float g_delta[MM*BB*2], g_cum[MM*BB*2];

__device__ __forceinline__ void mma16816(float* d, const uint32_t* a, const uint32_t* b) {
    asm volatile(
        "mma.sync.aligned.m16n8k16.row.col.f32.f16.f16.f32 "
        "{%0,%1,%2,%3}, {%4,%5,%6,%7}, {%8,%9}, {%0,%1,%2,%3};\n"
        : "+f"(d[0]), "+f"(d[1]), "+f"(d[2]), "+f"(d[3])
        : "r"(a[0]), "r"(a[1]), "r"(a[2]), "r"(a[3]), "r"(b[0]), "r"(b[1]));
}
__device__ __forceinline__ void ldsm4(uint32_t* r, const h16* p) {
    uint32_t a = (uint32_t)__cvta_generic_to_shared(p);
    asm volatile("ldmatrix.sync.aligned.m8n8.x4.shared.b16 {%0,%1,%2,%3}, [%4];\n"
                 : "=r"(r[0]), "=r"(r[1]), "=r"(r[2]), "=r"(r[3]) : "r"(a));
}
__device__ __forceinline__ void cpa(h16* s, const h16* g) {
    uint32_t sa = (uint32_t)__cvta_generic_to_shared(s);
    asm volatile("cp.async.cg.shared.global [%0], [%1], 16;\n" :: "r"(sa), "l"(g));
}
#define CP_COMMIT asm volatile("cp.async.commit_group;\n" ::: "memory")
#define CP_WAIT1  asm volatile("cp.async.wait_group 1;\n" ::: "memory")
#define CP_WAIT0  asm volatile("cp.async.wait_group 0;\n" ::: "memory")

__device__ __forceinline__ void splith(float v, h16& hi, h16& lo) {
    hi = __float2half_rn(v);
    lo = __float2half_rn(v - __half2float(hi));
}
__device__ __forceinline__ float sigf(float x) { return 1.f/(1.f+expf(-x)); }

// ---------- single prep kernel ----------
__global__ void k_prep_all(const float* __restrict__ ctx, const float* __restrict__ whh0,
                           const float* __restrict__ wih1, const float* __restrict__ whh1,
                           const float* __restrict__ wih0) {
    const int n1 = MM*G3*HH;
    const int N0 = BB*FF, N1 = N0 + 4*n1, N2 = N1 + MM*G3, N3 = N2 + MM*BB*2;
    for (int i = blockIdx.x*blockDim.x + threadIdx.x; i < N3; i += gridDim.x*blockDim.x) {
        if (i < N0) {
            h16 hi, lo; splith(ctx[i], hi, lo);
            g_ctx_hi[i] = hi; g_ctx_lo[i] = lo;
#pragma unroll
            for (int m = 0; m < MM; m++) {
                int o = m*BB*HH + i;
                g_h0_hi[0][o] = hi; g_h0_lo[0][o] = lo;
                g_h1_hi[0][o] = hi; g_h1_lo[0][o] = lo;
            }
        } else if (i < N1) {
            int j = i - N0, a = j / n1, e = j - a*n1;
            float v;
            if (a == 3) {
                int m = e / (G3*HH), r = (e - m*G3*HH) / HH, c = e % HH;
                v = wih0[((size_t)m*G3 + r)*IN0 + 2 + c];
            } else v = (a == 0 ? whh0 : (a == 1 ? wih1 : whh1))[e];
            h16 w = __float2half_rn(v);
            if      (a == 0) g_whh0[e] = w;
            else if (a == 1) g_wih1[e] = w;
            else if (a == 2) g_whh1[e] = w;
            else             g_wc[e]   = w;
        } else if (i < N2) {
            int j = i - N1;
            g_wp0[j*2+0] = wih0[(size_t)j*IN0 + 0];
            g_wp0[j*2+1] = wih0[(size_t)j*IN0 + 1];
        } else {
            int j = i - N2;
            g_delta[j] = 0.f; g_cum[j] = 0.f;
        }
    }
}

// ---------- gx0 = ctx @ wc^T + b_ih0 (once) ----------
__global__ void __launch_bounds__(128) k_gx0(const float* __restrict__ bih0) {
    const int m = blockIdx.z, rb = blockIdx.x, ub = blockIdx.y;
    __shared__ __align__(16) h16 sm[(2*64 + 32) * KP];
    h16* As = sm; h16* Ws = sm + 2*64*KP;
    const h16* Ap[2] = { g_ctx_hi, g_ctx_lo };
    const h16* W = g_wc + m*G3*HH;
    const int tid = threadIdx.x, lane = tid & 31, wid = tid >> 5;
    const int wm = wid & 1, wn = wid >> 1, gq = lane >> 2, tg = lane & 3;
    float acc[2][2][4];
#pragma unroll
    for (int a = 0; a < 2; a++)
#pragma unroll
    for (int b = 0; b < 2; b++)
#pragma unroll
    for (int e = 0; e < 4; e++) acc[a][b][e] = 0.f;
    for (int kc = 0; kc < 4; kc++) {
        const int k0 = kc * 64;
        for (int idx = tid; idx < 1024; idx += 128) {
            int t = idx >> 9, rem = idx & 511, r = rem >> 3, c = rem & 7;
            ((uint4*)As)[t*64*9 + r*9 + c] = ((const uint4*)(Ap[t] + (size_t)(rb*64+r)*HH + k0))[c];
        }
        for (int idx = tid; idx < 256; idx += 128) {
            int r = idx >> 3, c = idx & 7;
            ((uint4*)Ws)[r*9 + c] = ((const uint4*)(W + (size_t)(ub*32+r)*HH + k0))[c];
        }
        __syncthreads();
#pragma unroll
        for (int ks = 0; ks < 4; ks++) {
            const int kk = ks * 16;
            uint32_t afr[2][2][4];
#pragma unroll
            for (int hl = 0; hl < 2; hl++)
#pragma unroll
                for (int mf = 0; mf < 2; mf++) {
                    const h16* at = As + hl*64*KP + (wm*32+mf*16+gq)*KP + kk + tg*2;
                    afr[hl][mf][0] = *(const uint32_t*)at;
                    afr[hl][mf][1] = *(const uint32_t*)(at + 8*KP);
                    afr[hl][mf][2] = *(const uint32_t*)(at + 8);
                    afr[hl][mf][3] = *(const uint32_t*)(at + 8*KP + 8);
                }
            uint32_t bfr[2][2];
#pragma unroll
            for (int nf = 0; nf < 2; nf++) {
                const h16* wt = Ws + (wn*16+nf*8+gq)*KP + kk + tg*2;
                bfr[nf][0] = *(const uint32_t*)wt;
                bfr[nf][1] = *(const uint32_t*)(wt + 8);
            }
#pragma unroll
            for (int mf = 0; mf < 2; mf++)
#pragma unroll
                for (int nf = 0; nf < 2; nf++) {
                    mma16816(acc[mf][nf], afr[0][mf], bfr[nf]);
                    mma16816(acc[mf][nf], afr[1][mf], bfr[nf]);
                }
        }
        __syncthreads();
    }
#pragma unroll
    for (int mf = 0; mf < 2; mf++)
#pragma unroll
    for (int e = 0; e < 2; e++) {
        int row = rb*64 + wm*32 + mf*16 + gq + e*8;
#pragma unroll
        for (int nf = 0; nf < 2; nf++)
#pragma unroll
        for (int cc = 0; cc < 2; cc++) {
            int col = ub*32 + wn*16 + nf*8 + tg*2 + cc;
            g_gx0[((size_t)m*BB+row)*G3 + col] = acc[mf][nf][e*2+cc] + bih0[m*G3+col];
        }
    }
}

// ---------- layer0 fused (pipelined, ldmatrix, fp16x2) ----------
__global__ void __launch_bounds__(256, 2) k_l0(const float* __restrict__ bhh0, int p) {
    const int m = blockIdx.z, rb = blockIdx.x, ub = blockIdx.y, q = p^1;
    extern __shared__ __align__(16) h16 sm0[];
    h16* As = sm0;                      // 2 stages x 2 tiles x 64 x KP2
    h16* Ws = sm0 + 2*2*64*KP2;         // 2 stages x 3 tiles x 32 x KP2
    const h16* Ap[2] = { g_h0_hi[p] + m*BB*HH, g_h0_lo[p] + m*BB*HH };
    const h16* W = g_whh0 + m*G3*HH;
    const int tid = threadIdx.x, lane = tid & 31, wid = tid >> 5;
    const int wm = wid >> 1, wn = wid & 1, gq = lane >> 2, tg = lane & 3;
    const int ar = lane & 15, ac = (lane >> 4) * 8;
    const int br = ((lane >> 4) & 1) * 8 + (lane & 7), bc = ((lane >> 3) & 1) * 8;

    float acc[3][2][4];
#pragma unroll
    for (int g = 0; g < 3; g++)
#pragma unroll
    for (int b = 0; b < 2; b++)
#pragma unroll
    for (int e = 0; e < 4; e++) acc[g][b][e] = 0.f;

    auto load = [&](int s, int c) {
        for (int i = tid; i < 512; i += 256) {   // A: 2 x 64 x 4 chunks
            int t = i >> 8, rem = i & 255, r = rem >> 2, ch = rem & 3;
            cpa(As + ((s*2 + t)*64 + r)*KP2 + ch*8,
                Ap[t] + (size_t)(rb*64 + r)*HH + c*32 + ch*8);
        }
        for (int i = tid; i < 384; i += 256) {   // W: 3 x 32 x 4
            int g = i >> 7, rem = i & 127, r = rem >> 2, ch = rem & 3;
            cpa(Ws + ((s*3 + g)*32 + r)*KP2 + ch*8,
                W + (size_t)(g*HH + ub*32 + r)*HH + c*32 + ch*8);
        }
    };

    load(0, 0); CP_COMMIT;
    for (int c = 0; c < 8; c++) {
        if (c + 1 < 8) { load((c+1)&1, c+1); CP_COMMIT; CP_WAIT1; }
        else CP_WAIT0;
        __syncthreads();
        const int s = c & 1;
#pragma unroll
        for (int ks = 0; ks < 2; ks++) {
            const int kk = ks * 16;
            uint32_t afr[2][4];
#pragma unroll
            for (int hl = 0; hl < 2; hl++)
                ldsm4(afr[hl], As + ((s*2 + hl)*64 + wm*16 + ar)*KP2 + kk + ac);
#pragma unroll
            for (int g = 0; g < 3; g++) {
                uint32_t bfr[4];
                ldsm4(bfr, Ws + ((s*3 + g)*32 + wn*16 + br)*KP2 + kk + bc);
#pragma unroll
                for (int nf = 0; nf < 2; nf++) {
                    mma16816(acc[g][nf], afr[0], &bfr[nf*2]);
                    mma16816(acc[g][nf], afr[1], &bfr[nf*2]);
                }
            }
        }
        __syncthreads();
    }

    const float* bh = bhh0 + m*G3;
#pragma unroll
    for (int e = 0; e < 2; e++) {
        int row = rb*64 + wm*16 + gq + e*8;
        float px = g_delta[(m*BB+row)*2+0], py = g_delta[(m*BB+row)*2+1];
        size_t gxb = (size_t)(m*BB+row)*G3;
#pragma unroll
        for (int nf = 0; nf < 2; nf++)
#pragma unroll
        for (int cc = 0; cc < 2; cc++) {
            int u = ub*32 + wn*16 + nf*8 + tg*2 + cc;
            int ec = e*2+cc;
            const float* w0 = g_wp0 + (m*G3+u)*2;
            const float* w1p = g_wp0 + (m*G3+HH+u)*2;
            const float* w2p = g_wp0 + (m*G3+2*HH+u)*2;
            float xr = g_gx0[gxb+u]      + px*w0[0]  + py*w0[1];
            float xz = g_gx0[gxb+HH+u]   + px*w1p[0] + py*w1p[1];
            float xn = g_gx0[gxb+2*HH+u] + px*w2p[0] + py*w2p[1];
            float r = sigf(xr + acc[0][nf][ec] + bh[u]);
            float z = sigf(xz + acc[1][nf][ec] + bh[HH+u]);
            float n = tanhf(xn + r*(acc[2][nf][ec] + bh[2*HH+u]));
            size_t hix = (size_t)(m*BB+row)*HH + u;
            float hp = __half2float(g_h0_hi[p][hix]) + __half2float(g_h0_lo[p][hix]);
            float h = (1.f-z)*n + z*hp;
            h16 hhi, hlo; splith(h, hhi, hlo);
            g_h0_hi[q][hix] = hhi; g_h0_lo[q][hix] = hlo;
        }
    }
}

// ---------- layer1 fused (pipelined, ldmatrix, fp16x2) ----------
__global__ void __launch_bounds__(256, 2) k_l1(const float* __restrict__ bih1,
                                               const float* __restrict__ bhh1, int p) {
    const int m = blockIdx.z, rb = blockIdx.x, ub = blockIdx.y, q = p^1;
    extern __shared__ __align__(16) h16 sm1[];
    h16* As = sm1;                      // 2 x 4 x 64 x KP2
    h16* Ws = sm1 + 2*4*64*KP2;         // 2 x 6 x 32 x KP2
    const h16* Ap[4] = { g_h0_hi[q] + m*BB*HH, g_h0_lo[q] + m*BB*HH,
                         g_h1_hi[p] + m*BB*HH, g_h1_lo[p] + m*BB*HH };
    const h16* Wp[2] = { g_wih1 + m*G3*HH, g_whh1 + m*G3*HH };
    const int tid = threadIdx.x, lane = tid & 31, wid = tid >> 5;
    const int wm = wid >> 1, wn = wid & 1, gq = lane >> 2, tg = lane & 3;
    const int ar = lane & 15, ac = (lane >> 4) * 8;
    const int br = ((lane >> 4) & 1) * 8 + (lane & 7), bc = ((lane >> 3) & 1) * 8;

    float acc[2][3][2][4];
#pragma unroll
    for (int a = 0; a < 2; a++)
#pragma unroll
    for (int g = 0; g < 3; g++)
#pragma unroll
    for (int b = 0; b < 2; b++)
#pragma unroll
    for (int e = 0; e < 4; e++) acc[a][g][b][e] = 0.f;

    auto load = [&](int s, int c) {
        for (int i = tid; i < 1024; i += 256) {   // A: 4 x 64 x 4
            int t = i >> 8, rem = i & 255, r = rem >> 2, ch = rem & 3;
            cpa(As + ((s*4 + t)*64 + r)*KP2 + ch*8,
                Ap[t] + (size_t)(rb*64 + r)*HH + c*32 + ch*8);
        }
        for (int i = tid; i < 768; i += 256) {    // W: 6 x 32 x 4
            int t = i >> 7, rem = i & 127, r = rem >> 2, ch = rem & 3;
            int mat = t / 3, g = t % 3;
            cpa(Ws + ((s*6 + t)*32 + r)*KP2 + ch*8,
                Wp[mat] + (size_t)(g*HH + ub*32 + r)*HH + c*32 + ch*8);
        }
    };

    load(0, 0); CP_COMMIT;
    for (int c = 0; c < 8; c++) {
        if (c + 1 < 8) { load((c+1)&1, c+1); CP_COMMIT; CP_WAIT1; }
        else CP_WAIT0;
        __syncthreads();
        const int s = c & 1;
#pragma unroll
        for (int ks = 0; ks < 2; ks++) {
            const int kk = ks * 16;
#pragma unroll
            for (int mat = 0; mat < 2; mat++) {
                uint32_t afr[2][4];
#pragma unroll
                for (int hl = 0; hl < 2; hl++)
                    ldsm4(afr[hl], As + ((s*4 + mat*2 + hl)*64 + wm*16 + ar)*KP2 + kk + ac);
#pragma unroll
                for (int g = 0; g < 3; g++) {
                    uint32_t bfr[4];
                    ldsm4(bfr, Ws + ((s*6 + mat*3 + g)*32 + wn*16 + br)*KP2 + kk + bc);
#pragma unroll
                    for (int nf = 0; nf < 2; nf++) {
                        mma16816(acc[mat][g][nf], afr[0], &bfr[nf*2]);
                        mma16816(acc[mat][g][nf], afr[1], &bfr[nf*2]);
                    }
                }
            }
        }
        __syncthreads();
    }

    const float* bi = bih1 + m*G3; const float* bh = bhh1 + m*G3;
#pragma unroll
    for (int e = 0; e < 2; e++) {
        int row = rb*64 + wm*16 + gq + e*8;
#pragma unroll
        for (int nf = 0; nf < 2; nf++)
#pragma unroll
        for (int cc = 0; cc < 2; cc++) {
            int u = ub*32 + wn*16 + nf*8 + tg*2 + cc;
            int ec = e*2+cc;
            float r = sigf(acc[0][0][nf][ec] + bi[u]      + acc[1][0][nf][ec] + bh[u]);
            float z = sigf(acc[0][1][nf][ec] + bi[HH+u]   + acc[1][1][nf][ec] + bh[HH+u]);
            float n = tanhf(acc[0][2][nf][ec] + bi[2*HH+u] + r*(acc[1][2][nf][ec] + bh[2*HH+u]));
            size_t hix = (size_t)(m*BB+row)*HH + u;
            float hp = __half2float(g_h1_hi[p][hix]) + __half2float(g_h1_lo[p][hix]);
            float h = (1.f-z)*n + z*hp;
            h16 hhi, hlo; splith(h, hhi, hlo);
            g_h1_hi[q][hix] = hhi; g_h1_lo[q][hix] = hlo;
            g_h1f[hix] = h;
        }
    }
}

// ---------- delta + cumsum + output ----------
__global__ void k_delta(const float* __restrict__ ow, const float* __restrict__ ob,
                        float* __restrict__ out, int t) {
    int warp = (blockIdx.x * blockDim.x + threadIdx.x) >> 5;
    int lane = threadIdx.x & 31;
    if (warp >= MM*BB) return;
    int m = warp / BB, b = warp - m*BB;
    const float* h = g_h1f + (size_t)warp * HH;
    float a0 = 0.f, a1 = 0.f;
    for (int k = lane; k < HH; k += 32) {
        float hv = h[k];
        a0 += hv * __ldg(&ow[(m*2+0)*HH + k]);
        a1 += hv * __ldg(&ow[(m*2+1)*HH + k]);
    }
#pragma unroll
    for (int o = 16; o; o >>= 1) {
        a0 += __shfl_xor_sync(0xffffffffu, a0, o);
        a1 += __shfl_xor_sync(0xffffffffu, a1, o);
    }
    if (lane == 0) {
        a0 += ob[m*2+0]; a1 += ob[m*2+1];
        g_delta[warp*2+0] = a0; g_delta[warp*2+1] = a1;
        float c0 = g_cum[warp*2+0] + a0, c1 = g_cum[warp*2+1] + a1;
        g_cum[warp*2+0] = c0; g_cum[warp*2+1] = c1;
        size_t oo = (((size_t)b*MM + m)*TT + t)*2;
        out[oo] = c0; out[oo+1] = c1;
    }
}

// ---------- mode probs ----------
__global__ void k_modeprobs(const float* __restrict__ ctx,
                            const float* __restrict__ w1, const float* __restrict__ b1,
                            const float* __restrict__ w2, const float* __restrict__ b2,
                            float* __restrict__ probs) {
    int gw = (blockIdx.x * blockDim.x + threadIdx.x) >> 5;
    int lane = threadIdx.x & 31;
    int b0 = gw * 4;
    if (b0 >= BB) return;
    int u0 = lane * 2, u1 = u0 + 1;
    float acc[4][2];
#pragma unroll
    for (int r = 0; r < 4; r++) { acc[r][0] = 0.f; acc[r][1] = 0.f; }
    for (int k = 0; k < FF; k++) {
        float wa = __ldg(&w1[u0*FF+k]), wb = __ldg(&w1[u1*FF+k]);
#pragma unroll
        for (int r = 0; r < 4; r++) {
            float c = __ldg(&ctx[(size_t)(b0+r)*FF+k]);
            acc[r][0] += c*wa; acc[r][1] += c*wb;
        }
    }
#pragma unroll
    for (int r = 0; r < 4; r++) {
        float h0v = fmaxf(acc[r][0] + b1[u0], 0.f);
        float h1v = fmaxf(acc[r][1] + b1[u1], 0.f);
        float lg[3];
#pragma unroll
        for (int m = 0; m < 3; m++) {
            float p = h0v*w2[m*64+u0] + h1v*w2[m*64+u1];
#pragma unroll
            for (int o = 16; o; o >>= 1) p += __shfl_xor_sync(0xffffffffu, p, o);
            lg[m] = p + b2[m];
        }
        if (lane == 0) {
            float mx = fmaxf(lg[0], fmaxf(lg[1], lg[2]));
            float e0 = expf(lg[0]-mx), e1 = expf(lg[1]-mx), e2 = expf(lg[2]-mx);
            float s = e0+e1+e2;
            probs[(size_t)(b0+r)*MM+0] = e0/s;
            probs[(size_t)(b0+r)*MM+1] = e1/s;
            probs[(size_t)(b0+r)*MM+2] = e2/s;
        }
    }
}

extern "C" void kernel_launch(void* const* d_in, const int* in_sizes, int n_in,
                              void* d_out, int out_size) {
    const float* ctx  = (const float*)d_in[0];
    const float* w1   = (const float*)d_in[1];
    const float* b1   = (const float*)d_in[2];
    const float* w2   = (const float*)d_in[3];
    const float* b2   = (const float*)d_in[4];
    const float* wih0 = (const float*)d_in[5];
    const float* bih0 = (const float*)d_in[7];
    const float* bhh0 = (const float*)d_in[8];
    const float* bih1 = (const float*)d_in[11];
    const float* bhh1 = (const float*)d_in[12];
    const float* ow   = (const float*)d_in[13];
    const float* ob   = (const float*)d_in[14];
    float* out = (float*)d_out;
    float* probs = out + (size_t)BB*MM*TT*2;

    const int SM_L0 = (2*2*64 + 2*3*32) * KP2 * (int)sizeof(h16);   // 35840
    const int SM_L1 = (2*4*64 + 2*6*32) * KP2 * (int)sizeof(h16);   // 71680
    cudaFuncSetAttribute(k_l0, cudaFuncAttributeMaxDynamicSharedMemorySize, SM_L0);
    cudaFuncSetAttribute(k_l1, cudaFuncAttributeMaxDynamicSharedMemorySize, SM_L1);

    const int NPREP = BB*FF + 4*MM*G3*HH + MM*G3 + MM*BB*2;
    k_prep_all<<<(NPREP+255)/256, 256>>>(ctx, (const float*)d_in[6], (const float*)d_in[9],
                                         (const float*)d_in[10], wih0);

    dim3 g0(BB/64, G3/32, MM);
    k_gx0<<<g0, 128>>>(bih0);

    dim3 gl(BB/64, HH/32, MM);
    for (int t = 0; t < TT; t++) {
        int p = t & 1;
        k_l0<<<gl, 256, SM_L0>>>(bhh0, p);
        k_l1<<<gl, 256, SM_L1>>>(bih1, bhh1, p);
        k_delta<<<(MM*BB*32+127)/128, 128>>>(ow, ob, out, t);
    }

    k_modeprobs<<<256, 128>>>(ctx, w1, b1, w2, b2, probs);
}

// round 8
// speedup vs baseline: 1.5611x; 1.0114x over previous
#include <cuda_runtime.h>
#include <cuda_fp16.h>
#include <stdint.h>
#include <math.h>

#define BB 4096
#define FF 256
#define HH 256
#define MM 3
#define TT 30
#define G3 768
#define IN0 258
#define KP 72
#define KP2 40
#define S0 4   // pipeline stages layer0
#define S1 3   // pipeline stages layer1

typedef __half h16;

__device__ h16 g_ctx_hi[BB*FF], g_ctx_lo[BB*FF];
__device__ h16 g_h0_hi[2][MM*BB*HH], g_h0_lo[2][MM*BB*HH];
__device__ h16 g_h1_hi[2][MM*BB*HH], g_h1_lo[2][MM*BB*HH];
__device__ h16 g_whh0[MM*G3*HH];
__device__ h16 g_wih1[MM*G3*HH];
__device__ h16 g_whh1[MM*G3*HH];
__device__ h16 g_wc[MM*G3*HH];
__device__ float g_gx0[(size_t)MM*BB*G3];   // includes b_ih0
__device__ float g_wp0[MM*G3*2];            // w_ih0[:, :, 0:2] packed
__device__ float g_h1f[MM*BB*HH];
__device__ float g_delta[MM*BB*2], g_cum[MM*BB*2];

__device__ __forceinline__ void mma16816(float* d, const uint32_t* a, const uint32_t* b) {
    asm volatile(
        "mma.sync.aligned.m16n8k16.row.col.f32.f16.f16.f32 "
        "{%0,%1,%2,%3}, {%4,%5,%6,%7}, {%8,%9}, {%0,%1,%2,%3};\n"
        : "+f"(d[0]), "+f"(d[1]), "+f"(d[2]), "+f"(d[3])
        : "r"(a[0]), "r"(a[1]), "r"(a[2]), "r"(a[3]), "r"(b[0]), "r"(b[1]));
}
__device__ __forceinline__ void ldsm4(uint32_t* r, const h16* p) {
    uint32_t a = (uint32_t)__cvta_generic_to_shared(p);
    asm volatile("ldmatrix.sync.aligned.m8n8.x4.shared.b16 {%0,%1,%2,%3}, [%4];\n"
                 : "=r"(r[0]), "=r"(r[1]), "=r"(r[2]), "=r"(r[3]) : "r"(a));
}
__device__ __forceinline__ void cpa(h16* s, const h16* g) {
    uint32_t sa = (uint32_t)__cvta_generic_to_shared(s);
    asm volatile("cp.async.cg.shared.global [%0], [%1], 16;\n" :: "r"(sa), "l"(g));
}
#define CP_COMMIT   asm volatile("cp.async.commit_group;\n" ::: "memory")
#define CP_WAITG(n) asm volatile("cp.async.wait_group %0;\n" :: "n"(n) : "memory")

__device__ __forceinline__ void splith(float v, h16& hi, h16& lo) {
    hi = __float2half_rn(v);
    lo = __float2half_rn(v - __half2float(hi));
}
__device__ __forceinline__ float sigf(float x) { return 1.f/(1.f+expf(-x)); }

// ---------- single prep kernel ----------
__global__ void k_prep_all(const float* __restrict__ ctx, const float* __restrict__ whh0,
                           const float* __restrict__ wih1, const float* __restrict__ whh1,
                           const float* __restrict__ wih0) {
    const int n1 = MM*G3*HH;
    const int N0 = BB*FF, N1 = N0 + 4*n1, N2 = N1 + MM*G3, N3 = N2 + MM*BB*2;
    for (int i = blockIdx.x*blockDim.x + threadIdx.x; i < N3; i += gridDim.x*blockDim.x) {
        if (i < N0) {
            h16 hi, lo; splith(ctx[i], hi, lo);
            g_ctx_hi[i] = hi; g_ctx_lo[i] = lo;
#pragma unroll
            for (int m = 0; m < MM; m++) {
                int o = m*BB*HH + i;
                g_h0_hi[0][o] = hi; g_h0_lo[0][o] = lo;
                g_h1_hi[0][o] = hi; g_h1_lo[0][o] = lo;
            }
        } else if (i < N1) {
            int j = i - N0, a = j / n1, e = j - a*n1;
            float v;
            if (a == 3) {
                int m = e / (G3*HH), r = (e - m*G3*HH) / HH, c = e % HH;
                v = wih0[((size_t)m*G3 + r)*IN0 + 2 + c];
            } else v = (a == 0 ? whh0 : (a == 1 ? wih1 : whh1))[e];
            h16 w = __float2half_rn(v);
            if      (a == 0) g_whh0[e] = w;
            else if (a == 1) g_wih1[e] = w;
            else if (a == 2) g_whh1[e] = w;
            else             g_wc[e]   = w;
        } else if (i < N2) {
            int j = i - N1;
            g_wp0[j*2+0] = wih0[(size_t)j*IN0 + 0];
            g_wp0[j*2+1] = wih0[(size_t)j*IN0 + 1];
        } else {
            int j = i - N2;
            g_delta[j] = 0.f; g_cum[j] = 0.f;
        }
    }
}

// ---------- gx0 = ctx @ wc^T + b_ih0 (once) ----------
__global__ void __launch_bounds__(128) k_gx0(const float* __restrict__ bih0) {
    const int m = blockIdx.z, rb = blockIdx.x, ub = blockIdx.y;
    __shared__ __align__(16) h16 sm[(2*64 + 32) * KP];
    h16* As = sm; h16* Ws = sm + 2*64*KP;
    const h16* Ap[2] = { g_ctx_hi, g_ctx_lo };
    const h16* W = g_wc + m*G3*HH;
    const int tid = threadIdx.x, lane = tid & 31, wid = tid >> 5;
    const int wm = wid & 1, wn = wid >> 1, gq = lane >> 2, tg = lane & 3;
    float acc[2][2][4];
#pragma unroll
    for (int a = 0; a < 2; a++)
#pragma unroll
    for (int b = 0; b < 2; b++)
#pragma unroll
    for (int e = 0; e < 4; e++) acc[a][b][e] = 0.f;
    for (int kc = 0; kc < 4; kc++) {
        const int k0 = kc * 64;
        for (int idx = tid; idx < 1024; idx += 128) {
            int t = idx >> 9, rem = idx & 511, r = rem >> 3, c = rem & 7;
            ((uint4*)As)[t*64*9 + r*9 + c] = ((const uint4*)(Ap[t] + (size_t)(rb*64+r)*HH + k0))[c];
        }
        for (int idx = tid; idx < 256; idx += 128) {
            int r = idx >> 3, c = idx & 7;
            ((uint4*)Ws)[r*9 + c] = ((const uint4*)(W + (size_t)(ub*32+r)*HH + k0))[c];
        }
        __syncthreads();
#pragma unroll
        for (int ks = 0; ks < 4; ks++) {
            const int kk = ks * 16;
            uint32_t afr[2][2][4];
#pragma unroll
            for (int hl = 0; hl < 2; hl++)
#pragma unroll
                for (int mf = 0; mf < 2; mf++) {
                    const h16* at = As + hl*64*KP + (wm*32+mf*16+gq)*KP + kk + tg*2;
                    afr[hl][mf][0] = *(const uint32_t*)at;
                    afr[hl][mf][1] = *(const uint32_t*)(at + 8*KP);
                    afr[hl][mf][2] = *(const uint32_t*)(at + 8);
                    afr[hl][mf][3] = *(const uint32_t*)(at + 8*KP + 8);
                }
            uint32_t bfr[2][2];
#pragma unroll
            for (int nf = 0; nf < 2; nf++) {
                const h16* wt = Ws + (wn*16+nf*8+gq)*KP + kk + tg*2;
                bfr[nf][0] = *(const uint32_t*)wt;
                bfr[nf][1] = *(const uint32_t*)(wt + 8);
            }
#pragma unroll
            for (int mf = 0; mf < 2; mf++)
#pragma unroll
                for (int nf = 0; nf < 2; nf++) {
                    mma16816(acc[mf][nf], afr[0][mf], bfr[nf]);
                    mma16816(acc[mf][nf], afr[1][mf], bfr[nf]);
                }
        }
        __syncthreads();
    }
#pragma unroll
    for (int mf = 0; mf < 2; mf++)
#pragma unroll
    for (int e = 0; e < 2; e++) {
        int row = rb*64 + wm*32 + mf*16 + gq + e*8;
#pragma unroll
        for (int nf = 0; nf < 2; nf++)
#pragma unroll
        for (int cc = 0; cc < 2; cc++) {
            int col = ub*32 + wn*16 + nf*8 + tg*2 + cc;
            g_gx0[((size_t)m*BB+row)*G3 + col] = acc[mf][nf][e*2+cc] + bih0[m*G3+col];
        }
    }
}

// ---------- layer0 fused (4-stage pipeline, 1 sync/chunk) ----------
__global__ void __launch_bounds__(256, 2) k_l0(const float* __restrict__ bhh0, int p) {
    const int m = blockIdx.z, rb = blockIdx.x, ub = blockIdx.y, q = p^1;
    extern __shared__ __align__(16) h16 sm0[];
    h16* As = sm0;                        // S0 x 2 tiles x 64 x KP2
    h16* Ws = sm0 + S0*2*64*KP2;          // S0 x 3 tiles x 32 x KP2
    const h16* Ap[2] = { g_h0_hi[p] + m*BB*HH, g_h0_lo[p] + m*BB*HH };
    const h16* W = g_whh0 + m*G3*HH;
    const int tid = threadIdx.x, lane = tid & 31, wid = tid >> 5;
    const int wm = wid >> 1, wn = wid & 1, gq = lane >> 2, tg = lane & 3;
    const int ar = lane & 15, ac = (lane >> 4) * 8;
    const int br = ((lane >> 4) & 1) * 8 + (lane & 7), bc = ((lane >> 3) & 1) * 8;

    float acc[3][2][4];
#pragma unroll
    for (int g = 0; g < 3; g++)
#pragma unroll
    for (int b = 0; b < 2; b++)
#pragma unroll
    for (int e = 0; e < 4; e++) acc[g][b][e] = 0.f;

    auto load = [&](int s, int c) {
        for (int i = tid; i < 512; i += 256) {   // A: 2 x 64 x 4 chunks
            int t = i >> 8, rem = i & 255, r = rem >> 2, ch = rem & 3;
            cpa(As + ((s*2 + t)*64 + r)*KP2 + ch*8,
                Ap[t] + (size_t)(rb*64 + r)*HH + c*32 + ch*8);
        }
        for (int i = tid; i < 384; i += 256) {   // W: 3 x 32 x 4
            int g = i >> 7, rem = i & 127, r = rem >> 2, ch = rem & 3;
            cpa(Ws + ((s*3 + g)*32 + r)*KP2 + ch*8,
                W + (size_t)(g*HH + ub*32 + r)*HH + c*32 + ch*8);
        }
    };

#pragma unroll
    for (int s = 0; s < S0-1; s++) { load(s, s); CP_COMMIT; }
    for (int c = 0; c < 8; c++) {
        CP_WAITG(S0-2);
        __syncthreads();
        if (c + S0-1 < 8) load((c + S0-1) % S0, c + S0-1);
        CP_COMMIT;
        const int s = c % S0;
#pragma unroll
        for (int ks = 0; ks < 2; ks++) {
            const int kk = ks * 16;
            uint32_t afr[2][4];
#pragma unroll
            for (int hl = 0; hl < 2; hl++)
                ldsm4(afr[hl], As + ((s*2 + hl)*64 + wm*16 + ar)*KP2 + kk + ac);
#pragma unroll
            for (int g = 0; g < 3; g++) {
                uint32_t bfr[4];
                ldsm4(bfr, Ws + ((s*3 + g)*32 + wn*16 + br)*KP2 + kk + bc);
#pragma unroll
                for (int nf = 0; nf < 2; nf++) {
                    mma16816(acc[g][nf], afr[0], &bfr[nf*2]);
                    mma16816(acc[g][nf], afr[1], &bfr[nf*2]);
                }
            }
        }
    }

    const float* bh = bhh0 + m*G3;
#pragma unroll
    for (int e = 0; e < 2; e++) {
        int row = rb*64 + wm*16 + gq + e*8;
        float px = g_delta[(m*BB+row)*2+0], py = g_delta[(m*BB+row)*2+1];
        size_t gxb = (size_t)(m*BB+row)*G3;
#pragma unroll
        for (int nf = 0; nf < 2; nf++)
#pragma unroll
        for (int cc = 0; cc < 2; cc++) {
            int u = ub*32 + wn*16 + nf*8 + tg*2 + cc;
            int ec = e*2+cc;
            const float* w0 = g_wp0 + (m*G3+u)*2;
            const float* w1p = g_wp0 + (m*G3+HH+u)*2;
            const float* w2p = g_wp0 + (m*G3+2*HH+u)*2;
            float xr = g_gx0[gxb+u]      + px*w0[0]  + py*w0[1];
            float xz = g_gx0[gxb+HH+u]   + px*w1p[0] + py*w1p[1];
            float xn = g_gx0[gxb+2*HH+u] + px*w2p[0] + py*w2p[1];
            float r = sigf(xr + acc[0][nf][ec] + bh[u]);
            float z = sigf(xz + acc[1][nf][ec] + bh[HH+u]);
            float n = tanhf(xn + r*(acc[2][nf][ec] + bh[2*HH+u]));
            size_t hix = (size_t)(m*BB+row)*HH + u;
            float hp = __half2float(g_h0_hi[p][hix]) + __half2float(g_h0_lo[p][hix]);
            float h = (1.f-z)*n + z*hp;
            h16 hhi, hlo; splith(h, hhi, hlo);
            g_h0_hi[q][hix] = hhi; g_h0_lo[q][hix] = hlo;
        }
    }
}

// ---------- layer1 fused (3-stage pipeline, 1 sync/chunk) ----------
__global__ void __launch_bounds__(256, 2) k_l1(const float* __restrict__ bih1,
                                               const float* __restrict__ bhh1, int p) {
    const int m = blockIdx.z, rb = blockIdx.x, ub = blockIdx.y, q = p^1;
    extern __shared__ __align__(16) h16 sm1[];
    h16* As = sm1;                        // S1 x 4 x 64 x KP2
    h16* Ws = sm1 + S1*4*64*KP2;          // S1 x 6 x 32 x KP2
    const h16* Ap[4] = { g_h0_hi[q] + m*BB*HH, g_h0_lo[q] + m*BB*HH,
                         g_h1_hi[p] + m*BB*HH, g_h1_lo[p] + m*BB*HH };
    const h16* Wp[2] = { g_wih1 + m*G3*HH, g_whh1 + m*G3*HH };
    const int tid = threadIdx.x, lane = tid & 31, wid = tid >> 5;
    const int wm = wid >> 1, wn = wid & 1, gq = lane >> 2, tg = lane & 3;
    const int ar = lane & 15, ac = (lane >> 4) * 8;
    const int br = ((lane >> 4) & 1) * 8 + (lane & 7), bc = ((lane >> 3) & 1) * 8;

    float acc[2][3][2][4];
#pragma unroll
    for (int a = 0; a < 2; a++)
#pragma unroll
    for (int g = 0; g < 3; g++)
#pragma unroll
    for (int b = 0; b < 2; b++)
#pragma unroll
    for (int e = 0; e < 4; e++) acc[a][g][b][e] = 0.f;

    auto load = [&](int s, int c) {
        for (int i = tid; i < 1024; i += 256) {   // A: 4 x 64 x 4
            int t = i >> 8, rem = i & 255, r = rem >> 2, ch = rem & 3;
            cpa(As + ((s*4 + t)*64 + r)*KP2 + ch*8,
                Ap[t] + (size_t)(rb*64 + r)*HH + c*32 + ch*8);
        }
        for (int i = tid; i < 768; i += 256) {    // W: 6 x 32 x 4
            int t = i >> 7, rem = i & 127, r = rem >> 2, ch = rem & 3;
            int mat = t / 3, g = t % 3;
            cpa(Ws + ((s*6 + t)*32 + r)*KP2 + ch*8,
                Wp[mat] + (size_t)(g*HH + ub*32 + r)*HH + c*32 + ch*8);
        }
    };

#pragma unroll
    for (int s = 0; s < S1-1; s++) { load(s, s); CP_COMMIT; }
    for (int c = 0; c < 8; c++) {
        CP_WAITG(S1-2);
        __syncthreads();
        if (c + S1-1 < 8) load((c + S1-1) % S1, c + S1-1);
        CP_COMMIT;
        const int s = c % S1;
#pragma unroll
        for (int ks = 0; ks < 2; ks++) {
            const int kk = ks * 16;
#pragma unroll
            for (int mat = 0; mat < 2; mat++) {
                uint32_t afr[2][4];
#pragma unroll
                for (int hl = 0; hl < 2; hl++)
                    ldsm4(afr[hl], As + ((s*4 + mat*2 + hl)*64 + wm*16 + ar)*KP2 + kk + ac);
#pragma unroll
                for (int g = 0; g < 3; g++) {
                    uint32_t bfr[4];
                    ldsm4(bfr, Ws + ((s*6 + mat*3 + g)*32 + wn*16 + br)*KP2 + kk + bc);
#pragma unroll
                    for (int nf = 0; nf < 2; nf++) {
                        mma16816(acc[mat][g][nf], afr[0], &bfr[nf*2]);
                        mma16816(acc[mat][g][nf], afr[1], &bfr[nf*2]);
                    }
                }
            }
        }
    }

    const float* bi = bih1 + m*G3; const float* bh = bhh1 + m*G3;
#pragma unroll
    for (int e = 0; e < 2; e++) {
        int row = rb*64 + wm*16 + gq + e*8;
#pragma unroll
        for (int nf = 0; nf < 2; nf++)
#pragma unroll
        for (int cc = 0; cc < 2; cc++) {
            int u = ub*32 + wn*16 + nf*8 + tg*2 + cc;
            int ec = e*2+cc;
            float r = sigf(acc[0][0][nf][ec] + bi[u]      + acc[1][0][nf][ec] + bh[u]);
            float z = sigf(acc[0][1][nf][ec] + bi[HH+u]   + acc[1][1][nf][ec] + bh[HH+u]);
            float n = tanhf(acc[0][2][nf][ec] + bi[2*HH+u] + r*(acc[1][2][nf][ec] + bh[2*HH+u]));
            size_t hix = (size_t)(m*BB+row)*HH + u;
            float hp = __half2float(g_h1_hi[p][hix]) + __half2float(g_h1_lo[p][hix]);
            float h = (1.f-z)*n + z*hp;
            h16 hhi, hlo; splith(h, hhi, hlo);
            g_h1_hi[q][hix] = hhi; g_h1_lo[q][hix] = hlo;
            g_h1f[hix] = h;
        }
    }
}

// ---------- delta + cumsum + output ----------
__global__ void k_delta(const float* __restrict__ ow, const float* __restrict__ ob,
                        float* __restrict__ out, int t) {
    int warp = (blockIdx.x * blockDim.x + threadIdx.x) >> 5;
    int lane = threadIdx.x & 31;
    if (warp >= MM*BB) return;
    int m = warp / BB, b = warp - m*BB;
    const float* h = g_h1f + (size_t)warp * HH;
    float a0 = 0.f, a1 = 0.f;
    for (int k = lane; k < HH; k += 32) {
        float hv = h[k];
        a0 += hv * __ldg(&ow[(m*2+0)*HH + k]);
        a1 += hv * __ldg(&ow[(m*2+1)*HH + k]);
    }
#pragma unroll
    for (int o = 16; o; o >>= 1) {
        a0 += __shfl_xor_sync(0xffffffffu, a0, o);
        a1 += __shfl_xor_sync(0xffffffffu, a1, o);
    }
    if (lane == 0) {
        a0 += ob[m*2+0]; a1 += ob[m*2+1];
        g_delta[warp*2+0] = a0; g_delta[warp*2+1] = a1;
        float c0 = g_cum[warp*2+0] + a0, c1 = g_cum[warp*2+1] + a1;
        g_cum[warp*2+0] = c0; g_cum[warp*2+1] = c1;
        size_t oo = (((size_t)b*MM + m)*TT + t)*2;
        out[oo] = c0; out[oo+1] = c1;
    }
}

// ---------- mode probs ----------
__global__ void k_modeprobs(const float* __restrict__ ctx,
                            const float* __restrict__ w1, const float* __restrict__ b1,
                            const float* __restrict__ w2, const float* __restrict__ b2,
                            float* __restrict__ probs) {
    int gw = (blockIdx.x * blockDim.x + threadIdx.x) >> 5;
    int lane = threadIdx.x & 31;
    int b0 = gw * 4;
    if (b0 >= BB) return;
    int u0 = lane * 2, u1 = u0 + 1;
    float acc[4][2];
#pragma unroll
    for (int r = 0; r < 4; r++) { acc[r][0] = 0.f; acc[r][1] = 0.f; }
    for (int k = 0; k < FF; k++) {
        float wa = __ldg(&w1[u0*FF+k]), wb = __ldg(&w1[u1*FF+k]);
#pragma unroll
        for (int r = 0; r < 4; r++) {
            float c = __ldg(&ctx[(size_t)(b0+r)*FF+k]);
            acc[r][0] += c*wa; acc[r][1] += c*wb;
        }
    }
#pragma unroll
    for (int r = 0; r < 4; r++) {
        float h0v = fmaxf(acc[r][0] + b1[u0], 0.f);
        float h1v = fmaxf(acc[r][1] + b1[u1], 0.f);
        float lg[3];
#pragma unroll
        for (int m = 0; m < 3; m++) {
            float pp = h0v*w2[m*64+u0] + h1v*w2[m*64+u1];
#pragma unroll
            for (int o = 16; o; o >>= 1) pp += __shfl_xor_sync(0xffffffffu, pp, o);
            lg[m] = pp + b2[m];
        }
        if (lane == 0) {
            float mx = fmaxf(lg[0], fmaxf(lg[1], lg[2]));
            float e0 = expf(lg[0]-mx), e1 = expf(lg[1]-mx), e2 = expf(lg[2]-mx);
            float s = e0+e1+e2;
            probs[(size_t)(b0+r)*MM+0] = e0/s;
            probs[(size_t)(b0+r)*MM+1] = e1/s;
            probs[(size_t)(b0+r)*MM+2] = e2/s;
        }
    }
}

extern "C" void kernel_launch(void* const* d_in, const int* in_sizes, int n_in,
                              void* d_out, int out_size) {
    const float* ctx  = (const float*)d_in[0];
    const float* wih0 = (const float*)d_in[5];
    const float* bih0 = (const float*)d_in[7];
    const float* bhh0 = (const float*)d_in[8];
    const float* bih1 = (const float*)d_in[11];
    const float* bhh1 = (const float*)d_in[12];
    float* out = (float*)d_out;
    float* probs = out + (size_t)BB*MM*TT*2;

    const int SM_L0 = (S0*2*64 + S0*3*32) * KP2 * (int)sizeof(h16);   // 71680
    const int SM_L1 = (S1*4*64 + S1*6*32) * KP2 * (int)sizeof(h16);   // 107520
    cudaFuncSetAttribute(k_l0, cudaFuncAttributeMaxDynamicSharedMemorySize, SM_L0);
    cudaFuncSetAttribute(k_l1, cudaFuncAttributeMaxDynamicSharedMemorySize, SM_L1);

    const int NPREP = BB*FF + 4*MM*G3*HH + MM*G3 + MM*BB*2;
    k_prep_all<<<(NPREP+255)/256, 256>>>(ctx, (const float*)d_in[6], (const float*)d_in[9],
                                         (const float*)d_in[10], wih0);

    dim3 g0(BB/64, G3/32, MM);
    k_gx0<<<g0, 128>>>(bih0);

    dim3 gl(BB/64, HH/32, MM);
    for (int t = 0; t < TT; t++) {
        int p = t & 1;
        k_l0<<<gl, 256, SM_L0>>>(bhh0, p);
        k_l1<<<gl, 256, SM_L1>>>(bih1, bhh1, p);
        k_delta<<<(MM*BB*32+127)/128, 128>>>((const float*)d_in[13], (const float*)d_in[14], out, t);
    }

    k_modeprobs<<<256, 128>>>(ctx, (const float*)d_in[1], (const float*)d_in[2],
                              (const float*)d_in[3], (const float*)d_in[4], probs);
}

// round 9
// speedup vs baseline: 2.0378x; 1.3054x over previous
#include <cuda_runtime.h>
#include <cuda_fp16.h>
#include <stdint.h>
#include <math.h>

#define BB 4096
#define FF 256
#define HH 256
#define MM 3
#define TT 30
#define G3 768
#define IN0 258
#define KP 72
#define KP2 40
#define S0 4
#define S1 4

typedef __half h16;

__device__ h16 g_ctx_hi[BB*FF], g_ctx_lo[BB*FF];
__device__ h16 g_h0[2][MM*BB*HH];            // fp16 GEMM operand (double buffered)
__device__ h16 g_h1[2][MM*BB*HH];
__device__ float g_h0f32[MM*BB*HH];          // exact fp32 recurrence state
__device__ float g_h1f[MM*BB*HH];            // exact fp32 state (also read by k_delta)
__device__ h16 g_whh0[MM*G3*HH];
__device__ h16 g_wih1[MM*G3*HH];
__device__ h16 g_whh1[MM*G3*HH];
__device__ h16 g_wc[MM*G3*HH];
__device__ float g_gx0[(size_t)MM*BB*G3];    // includes b_ih0
__device__ float g_wp0[MM*G3*2];             // w_ih0[:, :, 0:2] packed
__device__ float g_delta[MM*BB*2], g_cum[MM*BB*2];

__device__ __forceinline__ void mma16816(float* d, const uint32_t* a, const uint32_t* b) {
    asm volatile(
        "mma.sync.aligned.m16n8k16.row.col.f32.f16.f16.f32 "
        "{%0,%1,%2,%3}, {%4,%5,%6,%7}, {%8,%9}, {%0,%1,%2,%3};\n"
        : "+f"(d[0]), "+f"(d[1]), "+f"(d[2]), "+f"(d[3])
        : "r"(a[0]), "r"(a[1]), "r"(a[2]), "r"(a[3]), "r"(b[0]), "r"(b[1]));
}
__device__ __forceinline__ void ldsm4(uint32_t* r, const h16* p) {
    uint32_t a = (uint32_t)__cvta_generic_to_shared(p);
    asm volatile("ldmatrix.sync.aligned.m8n8.x4.shared.b16 {%0,%1,%2,%3}, [%4];\n"
                 : "=r"(r[0]), "=r"(r[1]), "=r"(r[2]), "=r"(r[3]) : "r"(a));
}
__device__ __forceinline__ void cpa(h16* s, const h16* g) {
    uint32_t sa = (uint32_t)__cvta_generic_to_shared(s);
    asm volatile("cp.async.cg.shared.global [%0], [%1], 16;\n" :: "r"(sa), "l"(g));
}
#define CP_COMMIT   asm volatile("cp.async.commit_group;\n" ::: "memory")
#define CP_WAITG(n) asm volatile("cp.async.wait_group %0;\n" :: "n"(n) : "memory")

__device__ __forceinline__ void splith(float v, h16& hi, h16& lo) {
    hi = __float2half_rn(v);
    lo = __float2half_rn(v - __half2float(hi));
}
__device__ __forceinline__ float sigf(float x) { return 1.f/(1.f+expf(-x)); }

// ---------- single prep kernel ----------
__global__ void k_prep_all(const float* __restrict__ ctx, const float* __restrict__ whh0,
                           const float* __restrict__ wih1, const float* __restrict__ whh1,
                           const float* __restrict__ wih0) {
    const int n1 = MM*G3*HH;
    const int N0 = BB*FF, N1 = N0 + 4*n1, N2 = N1 + MM*G3, N3 = N2 + MM*BB*2;
    for (int i = blockIdx.x*blockDim.x + threadIdx.x; i < N3; i += gridDim.x*blockDim.x) {
        if (i < N0) {
            float v = ctx[i];
            h16 hi, lo; splith(v, hi, lo);
            g_ctx_hi[i] = hi; g_ctx_lo[i] = lo;
#pragma unroll
            for (int m = 0; m < MM; m++) {
                int o = m*BB*HH + i;
                g_h0[0][o] = hi; g_h1[0][o] = hi;
                g_h0f32[o] = v; g_h1f[o] = v;
            }
        } else if (i < N1) {
            int j = i - N0, a = j / n1, e = j - a*n1;
            float v;
            if (a == 3) {
                int m = e / (G3*HH), r = (e - m*G3*HH) / HH, c = e % HH;
                v = wih0[((size_t)m*G3 + r)*IN0 + 2 + c];
            } else v = (a == 0 ? whh0 : (a == 1 ? wih1 : whh1))[e];
            h16 w = __float2half_rn(v);
            if      (a == 0) g_whh0[e] = w;
            else if (a == 1) g_wih1[e] = w;
            else if (a == 2) g_whh1[e] = w;
            else             g_wc[e]   = w;
        } else if (i < N2) {
            int j = i - N1;
            g_wp0[j*2+0] = wih0[(size_t)j*IN0 + 0];
            g_wp0[j*2+1] = wih0[(size_t)j*IN0 + 1];
        } else {
            int j = i - N2;
            g_delta[j] = 0.f; g_cum[j] = 0.f;
        }
    }
}

// ---------- gx0 = ctx @ wc^T + b_ih0 (once, ctx hi+lo for precision) ----------
__global__ void __launch_bounds__(128) k_gx0(const float* __restrict__ bih0) {
    const int m = blockIdx.z, rb = blockIdx.x, ub = blockIdx.y;
    __shared__ __align__(16) h16 sm[(2*64 + 32) * KP];
    h16* As = sm; h16* Ws = sm + 2*64*KP;
    const h16* Ap[2] = { g_ctx_hi, g_ctx_lo };
    const h16* W = g_wc + m*G3*HH;
    const int tid = threadIdx.x, lane = tid & 31, wid = tid >> 5;
    const int wm = wid & 1, wn = wid >> 1, gq = lane >> 2, tg = lane & 3;
    float acc[2][2][4];
#pragma unroll
    for (int a = 0; a < 2; a++)
#pragma unroll
    for (int b = 0; b < 2; b++)
#pragma unroll
    for (int e = 0; e < 4; e++) acc[a][b][e] = 0.f;
    for (int kc = 0; kc < 4; kc++) {
        const int k0 = kc * 64;
        for (int idx = tid; idx < 1024; idx += 128) {
            int t = idx >> 9, rem = idx & 511, r = rem >> 3, c = rem & 7;
            ((uint4*)As)[t*64*9 + r*9 + c] = ((const uint4*)(Ap[t] + (size_t)(rb*64+r)*HH + k0))[c];
        }
        for (int idx = tid; idx < 256; idx += 128) {
            int r = idx >> 3, c = idx & 7;
            ((uint4*)Ws)[r*9 + c] = ((const uint4*)(W + (size_t)(ub*32+r)*HH + k0))[c];
        }
        __syncthreads();
#pragma unroll
        for (int ks = 0; ks < 4; ks++) {
            const int kk = ks * 16;
            uint32_t afr[2][2][4];
#pragma unroll
            for (int hl = 0; hl < 2; hl++)
#pragma unroll
                for (int mf = 0; mf < 2; mf++) {
                    const h16* at = As + hl*64*KP + (wm*32+mf*16+gq)*KP + kk + tg*2;
                    afr[hl][mf][0] = *(const uint32_t*)at;
                    afr[hl][mf][1] = *(const uint32_t*)(at + 8*KP);
                    afr[hl][mf][2] = *(const uint32_t*)(at + 8);
                    afr[hl][mf][3] = *(const uint32_t*)(at + 8*KP + 8);
                }
            uint32_t bfr[2][2];
#pragma unroll
            for (int nf = 0; nf < 2; nf++) {
                const h16* wt = Ws + (wn*16+nf*8+gq)*KP + kk + tg*2;
                bfr[nf][0] = *(const uint32_t*)wt;
                bfr[nf][1] = *(const uint32_t*)(wt + 8);
            }
#pragma unroll
            for (int mf = 0; mf < 2; mf++)
#pragma unroll
                for (int nf = 0; nf < 2; nf++) {
                    mma16816(acc[mf][nf], afr[0][mf], bfr[nf]);
                    mma16816(acc[mf][nf], afr[1][mf], bfr[nf]);
                }
        }
        __syncthreads();
    }
#pragma unroll
    for (int mf = 0; mf < 2; mf++)
#pragma unroll
    for (int e = 0; e < 2; e++) {
        int row = rb*64 + wm*32 + mf*16 + gq + e*8;
#pragma unroll
        for (int nf = 0; nf < 2; nf++)
#pragma unroll
        for (int cc = 0; cc < 2; cc++) {
            int col = ub*32 + wn*16 + nf*8 + tg*2 + cc;
            g_gx0[((size_t)m*BB+row)*G3 + col] = acc[mf][nf][e*2+cc] + bih0[m*G3+col];
        }
    }
}

// ---------- layer0 fused (single fp16 A, 4-stage pipeline) ----------
__global__ void __launch_bounds__(256, 3) k_l0(const float* __restrict__ bhh0, int p) {
    const int m = blockIdx.z, rb = blockIdx.x, ub = blockIdx.y, q = p^1;
    extern __shared__ __align__(16) h16 sm0[];
    h16* As = sm0;                        // S0 x 64 x KP2
    h16* Ws = sm0 + S0*64*KP2;            // S0 x 3 x 32 x KP2
    const h16* A = g_h0[p] + m*BB*HH;
    const h16* W = g_whh0 + m*G3*HH;
    const int tid = threadIdx.x, lane = tid & 31, wid = tid >> 5;
    const int wm = wid >> 1, wn = wid & 1, gq = lane >> 2, tg = lane & 3;
    const int ar = lane & 15, ac = (lane >> 4) * 8;
    const int br = ((lane >> 4) & 1) * 8 + (lane & 7), bc = ((lane >> 3) & 1) * 8;

    float acc[3][2][4];
#pragma unroll
    for (int g = 0; g < 3; g++)
#pragma unroll
    for (int b = 0; b < 2; b++)
#pragma unroll
    for (int e = 0; e < 4; e++) acc[g][b][e] = 0.f;

    auto load = [&](int s, int c) {
        for (int i = tid; i < 256; i += 256) {   // A: 64 x 4
            int r = i >> 2, ch = i & 3;
            cpa(As + (s*64 + r)*KP2 + ch*8, A + (size_t)(rb*64 + r)*HH + c*32 + ch*8);
        }
        for (int i = tid; i < 384; i += 256) {   // W: 3 x 32 x 4
            int g = i >> 7, rem = i & 127, r = rem >> 2, ch = rem & 3;
            cpa(Ws + ((s*3 + g)*32 + r)*KP2 + ch*8,
                W + (size_t)(g*HH + ub*32 + r)*HH + c*32 + ch*8);
        }
    };

#pragma unroll
    for (int s = 0; s < S0-1; s++) { load(s, s); CP_COMMIT; }
    for (int c = 0; c < 8; c++) {
        CP_WAITG(S0-2);
        __syncthreads();
        if (c + S0-1 < 8) load((c + S0-1) % S0, c + S0-1);
        CP_COMMIT;
        const int s = c % S0;
#pragma unroll
        for (int ks = 0; ks < 2; ks++) {
            const int kk = ks * 16;
            uint32_t afr[4];
            ldsm4(afr, As + (s*64 + wm*16 + ar)*KP2 + kk + ac);
#pragma unroll
            for (int g = 0; g < 3; g++) {
                uint32_t bfr[4];
                ldsm4(bfr, Ws + ((s*3 + g)*32 + wn*16 + br)*KP2 + kk + bc);
                mma16816(acc[g][0], afr, &bfr[0]);
                mma16816(acc[g][1], afr, &bfr[2]);
            }
        }
    }

    const float* bh = bhh0 + m*G3;
#pragma unroll
    for (int e = 0; e < 2; e++) {
        int row = rb*64 + wm*16 + gq + e*8;
        float px = g_delta[(m*BB+row)*2+0], py = g_delta[(m*BB+row)*2+1];
        size_t gxb = (size_t)(m*BB+row)*G3;
#pragma unroll
        for (int nf = 0; nf < 2; nf++)
#pragma unroll
        for (int cc = 0; cc < 2; cc++) {
            int u = ub*32 + wn*16 + nf*8 + tg*2 + cc;
            int ec = e*2+cc;
            const float* w0 = g_wp0 + (m*G3+u)*2;
            const float* w1p = g_wp0 + (m*G3+HH+u)*2;
            const float* w2p = g_wp0 + (m*G3+2*HH+u)*2;
            float xr = g_gx0[gxb+u]      + px*w0[0]  + py*w0[1];
            float xz = g_gx0[gxb+HH+u]   + px*w1p[0] + py*w1p[1];
            float xn = g_gx0[gxb+2*HH+u] + px*w2p[0] + py*w2p[1];
            float r = sigf(xr + acc[0][nf][ec] + bh[u]);
            float z = sigf(xz + acc[1][nf][ec] + bh[HH+u]);
            float n = tanhf(xn + r*(acc[2][nf][ec] + bh[2*HH+u]));
            size_t hix = (size_t)(m*BB+row)*HH + u;
            float h = (1.f-z)*n + z*g_h0f32[hix];
            g_h0f32[hix] = h;
            g_h0[q][hix] = __float2half_rn(h);
        }
    }
}

// ---------- layer1 fused (single fp16 A, 4-stage pipeline) ----------
__global__ void __launch_bounds__(256, 2) k_l1(const float* __restrict__ bih1,
                                               const float* __restrict__ bhh1, int p) {
    const int m = blockIdx.z, rb = blockIdx.x, ub = blockIdx.y, q = p^1;
    extern __shared__ __align__(16) h16 sm1[];
    h16* As = sm1;                        // S1 x 2 x 64 x KP2
    h16* Ws = sm1 + S1*2*64*KP2;          // S1 x 6 x 32 x KP2
    const h16* Ap[2] = { g_h0[q] + m*BB*HH, g_h1[p] + m*BB*HH };
    const h16* Wp[2] = { g_wih1 + m*G3*HH, g_whh1 + m*G3*HH };
    const int tid = threadIdx.x, lane = tid & 31, wid = tid >> 5;
    const int wm = wid >> 1, wn = wid & 1, gq = lane >> 2, tg = lane & 3;
    const int ar = lane & 15, ac = (lane >> 4) * 8;
    const int br = ((lane >> 4) & 1) * 8 + (lane & 7), bc = ((lane >> 3) & 1) * 8;

    float acc[2][3][2][4];
#pragma unroll
    for (int a = 0; a < 2; a++)
#pragma unroll
    for (int g = 0; g < 3; g++)
#pragma unroll
    for (int b = 0; b < 2; b++)
#pragma unroll
    for (int e = 0; e < 4; e++) acc[a][g][b][e] = 0.f;

    auto load = [&](int s, int c) {
        for (int i = tid; i < 512; i += 256) {   // A: 2 x 64 x 4
            int t = i >> 8, rem = i & 255, r = rem >> 2, ch = rem & 3;
            cpa(As + ((s*2 + t)*64 + r)*KP2 + ch*8,
                Ap[t] + (size_t)(rb*64 + r)*HH + c*32 + ch*8);
        }
        for (int i = tid; i < 768; i += 256) {   // W: 6 x 32 x 4
            int t = i >> 7, rem = i & 127, r = rem >> 2, ch = rem & 3;
            int mat = t / 3, g = t % 3;
            cpa(Ws + ((s*6 + t)*32 + r)*KP2 + ch*8,
                Wp[mat] + (size_t)(g*HH + ub*32 + r)*HH + c*32 + ch*8);
        }
    };

#pragma unroll
    for (int s = 0; s < S1-1; s++) { load(s, s); CP_COMMIT; }
    for (int c = 0; c < 8; c++) {
        CP_WAITG(S1-2);
        __syncthreads();
        if (c + S1-1 < 8) load((c + S1-1) % S1, c + S1-1);
        CP_COMMIT;
        const int s = c % S1;
#pragma unroll
        for (int ks = 0; ks < 2; ks++) {
            const int kk = ks * 16;
#pragma unroll
            for (int mat = 0; mat < 2; mat++) {
                uint32_t afr[4];
                ldsm4(afr, As + ((s*2 + mat)*64 + wm*16 + ar)*KP2 + kk + ac);
#pragma unroll
                for (int g = 0; g < 3; g++) {
                    uint32_t bfr[4];
                    ldsm4(bfr, Ws + ((s*6 + mat*3 + g)*32 + wn*16 + br)*KP2 + kk + bc);
                    mma16816(acc[mat][g][0], afr, &bfr[0]);
                    mma16816(acc[mat][g][1], afr, &bfr[2]);
                }
            }
        }
    }

    const float* bi = bih1 + m*G3; const float* bh = bhh1 + m*G3;
#pragma unroll
    for (int e = 0; e < 2; e++) {
        int row = rb*64 + wm*16 + gq + e*8;
#pragma unroll
        for (int nf = 0; nf < 2; nf++)
#pragma unroll
        for (int cc = 0; cc < 2; cc++) {
            int u = ub*32 + wn*16 + nf*8 + tg*2 + cc;
            int ec = e*2+cc;
            float r = sigf(acc[0][0][nf][ec] + bi[u]      + acc[1][0][nf][ec] + bh[u]);
            float z = sigf(acc[0][1][nf][ec] + bi[HH+u]   + acc[1][1][nf][ec] + bh[HH+u]);
            float n = tanhf(acc[0][2][nf][ec] + bi[2*HH+u] + r*(acc[1][2][nf][ec] + bh[2*HH+u]));
            size_t hix = (size_t)(m*BB+row)*HH + u;
            float h = (1.f-z)*n + z*g_h1f[hix];
            g_h1f[hix] = h;
            g_h1[q][hix] = __float2half_rn(h);
        }
    }
}

// ---------- delta + cumsum + output ----------
__global__ void k_delta(const float* __restrict__ ow, const float* __restrict__ ob,
                        float* __restrict__ out, int t) {
    int warp = (blockIdx.x * blockDim.x + threadIdx.x) >> 5;
    int lane = threadIdx.x & 31;
    if (warp >= MM*BB) return;
    int m = warp / BB, b = warp - m*BB;
    const float* h = g_h1f + (size_t)warp * HH;
    float a0 = 0.f, a1 = 0.f;
    for (int k = lane; k < HH; k += 32) {
        float hv = h[k];
        a0 += hv * __ldg(&ow[(m*2+0)*HH + k]);
        a1 += hv * __ldg(&ow[(m*2+1)*HH + k]);
    }
#pragma unroll
    for (int o = 16; o; o >>= 1) {
        a0 += __shfl_xor_sync(0xffffffffu, a0, o);
        a1 += __shfl_xor_sync(0xffffffffu, a1, o);
    }
    if (lane == 0) {
        a0 += ob[m*2+0]; a1 += ob[m*2+1];
        g_delta[warp*2+0] = a0; g_delta[warp*2+1] = a1;
        float c0 = g_cum[warp*2+0] + a0, c1 = g_cum[warp*2+1] + a1;
        g_cum[warp*2+0] = c0; g_cum[warp*2+1] = c1;
        size_t oo = (((size_t)b*MM + m)*TT + t)*2;
        out[oo] = c0; out[oo+1] = c1;
    }
}

// ---------- mode probs ----------
__global__ void k_modeprobs(const float* __restrict__ ctx,
                            const float* __restrict__ w1, const float* __restrict__ b1,
                            const float* __restrict__ w2, const float* __restrict__ b2,
                            float* __restrict__ probs) {
    int gw = (blockIdx.x * blockDim.x + threadIdx.x) >> 5;
    int lane = threadIdx.x & 31;
    int b0 = gw * 4;
    if (b0 >= BB) return;
    int u0 = lane * 2, u1 = u0 + 1;
    float acc[4][2];
#pragma unroll
    for (int r = 0; r < 4; r++) { acc[r][0] = 0.f; acc[r][1] = 0.f; }
    for (int k = 0; k < FF; k++) {
        float wa = __ldg(&w1[u0*FF+k]), wb = __ldg(&w1[u1*FF+k]);
#pragma unroll
        for (int r = 0; r < 4; r++) {
            float c = __ldg(&ctx[(size_t)(b0+r)*FF+k]);
            acc[r][0] += c*wa; acc[r][1] += c*wb;
        }
    }
#pragma unroll
    for (int r = 0; r < 4; r++) {
        float h0v = fmaxf(acc[r][0] + b1[u0], 0.f);
        float h1v = fmaxf(acc[r][1] + b1[u1], 0.f);
        float lg[3];
#pragma unroll
        for (int m = 0; m < 3; m++) {
            float pp = h0v*w2[m*64+u0] + h1v*w2[m*64+u1];
#pragma unroll
            for (int o = 16; o; o >>= 1) pp += __shfl_xor_sync(0xffffffffu, pp, o);
            lg[m] = pp + b2[m];
        }
        if (lane == 0) {
            float mx = fmaxf(lg[0], fmaxf(lg[1], lg[2]));
            float e0 = expf(lg[0]-mx), e1 = expf(lg[1]-mx), e2 = expf(lg[2]-mx);
            float s = e0+e1+e2;
            probs[(size_t)(b0+r)*MM+0] = e0/s;
            probs[(size_t)(b0+r)*MM+1] = e1/s;
            probs[(size_t)(b0+r)*MM+2] = e2/s;
        }
    }
}

extern "C" void kernel_launch(void* const* d_in, const int* in_sizes, int n_in,
                              void* d_out, int out_size) {
    const float* ctx  = (const float*)d_in[0];
    const float* wih0 = (const float*)d_in[5];
    const float* bih0 = (const float*)d_in[7];
    const float* bhh0 = (const float*)d_in[8];
    const float* bih1 = (const float*)d_in[11];
    const float* bhh1 = (const float*)d_in[12];
    float* out = (float*)d_out;
    float* probs = out + (size_t)BB*MM*TT*2;

    const int SM_L0 = (S0*64 + S0*3*32) * KP2 * (int)sizeof(h16);     // 51200
    const int SM_L1 = (S1*2*64 + S1*6*32) * KP2 * (int)sizeof(h16);   // 102400
    cudaFuncSetAttribute(k_l0, cudaFuncAttributeMaxDynamicSharedMemorySize, SM_L0);
    cudaFuncSetAttribute(k_l1, cudaFuncAttributeMaxDynamicSharedMemorySize, SM_L1);

    const int NPREP = BB*FF + 4*MM*G3*HH + MM*G3 + MM*BB*2;
    k_prep_all<<<(NPREP+255)/256, 256>>>(ctx, (const float*)d_in[6], (const float*)d_in[9],
                                         (const float*)d_in[10], wih0);

    dim3 g0(BB/64, G3/32, MM);
    k_gx0<<<g0, 128>>>(bih0);

    dim3 gl(BB/64, HH/32, MM);
    for (int t = 0; t < TT; t++) {
        int p = t & 1;
        k_l0<<<gl, 256, SM_L0>>>(bhh0, p);
        k_l1<<<gl, 256, SM_L1>>>(bih1, bhh1, p);
        k_delta<<<(MM*BB*32+127)/128, 128>>>((const float*)d_in[13], (const float*)d_in[14], out, t);
    }

    k_modeprobs<<<256, 128>>>(ctx, (const float*)d_in[1], (const float*)d_in[2],
                              (const float*)d_in[3], (const float*)d_in[4], probs);
}